// round 6
// baseline (speedup 1.0000x reference)
#include <cuda_runtime.h>
#include <cuda_bf16.h>
#include <cstdint>

#define B 64
#define T 512
#define F 256
#define C 1024
#define KOUT 256
#define BC (B * C)
#define WROW (F + C)          // 1280 floats per g_w/a_w row

// ---------------- recurrent kernel config --------------------------------
#define RCTA 128              // (cg 0..63) x (batch-half 0..1)
#define NCG  64               // cell groups
#define RTHR 256
#define CPC  16               // cells per CTA  (A tile M = 32 = 16 a + 16 g)
#define NB   32               // batches per CTA
#define APITCH 1032           // smem A pitch (bf16)
#define BPITCH 136            // smem B pitch (bf16)
#define A_BYTES (64 * APITCH * 2)              // rows 0-31 hi, 32-63 lo
#define B_HALF  (NB * BPITCH * 2)              // 8704 per hi or lo tile
#define B_STAGE (2 * B_HALF)                   // 17408
#define SB_OFF(s) (A_BYTES + (s) * B_STAGE)
#define RED_OFF (A_BYTES + 2 * B_STAGE)
#define RSMEM (RED_OFF + 4096)

// ---------------- bf16 GEMM (pre/out) config -----------------------------
#define GP 72                                   // smem pitch (bf16)
#define GSTG (128 * GP * 2)                     // 18432 B per operand stage
#define GSTAGE (2 * GSTG)                       // 36864
#define GSMEM (3 * GSTAGE)                      // 110592

// ---------------- device scratch -----------------------------------------
__device__ __align__(16) float g_U [(size_t)T * BC];
__device__ __align__(16) float g_GX[(size_t)T * BC];
__device__ __align__(16) float g_AX[(size_t)T * BC];
__device__ __align__(16) __nv_bfloat16 g_hshi[(size_t)(T + 1) * BC]; // h slots
__device__ __align__(16) __nv_bfloat16 g_hslo[(size_t)(T + 1) * BC];
__device__ __align__(16) __nv_bfloat16 g_Awhi[NCG * 32 * C];  // rec weights
__device__ __align__(16) __nv_bfloat16 g_Awlo[NCG * 32 * C];
__device__ __align__(16) __nv_bfloat16 g_xhi[(size_t)B * T * F];
__device__ __align__(16) __nv_bfloat16 g_xlo[(size_t)B * T * F];
__device__ __align__(16) __nv_bfloat16 g_pwhi[3 * C * F];     // u/gF/aF rows
__device__ __align__(16) __nv_bfloat16 g_pwlo[3 * C * F];
__device__ __align__(16) __nv_bfloat16 g_owhi[KOUT * C];
__device__ __align__(16) __nv_bfloat16 g_owlo[KOUT * C];
__device__ unsigned g_flag[2][8];

// ---------------- helpers -------------------------------------------------
__device__ __forceinline__ uint32_t smem_u32(const void* p) {
    uint32_t a;
    asm("{ .reg .u64 t; cvta.to.shared.u64 t, %1; cvt.u32.u64 %0, t; }"
        : "=r"(a) : "l"(p));
    return a;
}
__device__ __forceinline__ void cpa16(uint32_t dst, const void* src) {
    asm volatile("cp.async.cg.shared.global [%0], [%1], 16;"
                 :: "r"(dst), "l"(src) : "memory");
}
#define CPA_COMMIT() asm volatile("cp.async.commit_group;" ::: "memory")
#define CPA_WAIT(n)  asm volatile("cp.async.wait_group %0;" :: "n"(n) : "memory")

__device__ __forceinline__ void mma16816(float* d, const uint32_t* a,
                                         const uint32_t* b) {
    asm volatile(
        "mma.sync.aligned.m16n8k16.row.col.f32.bf16.bf16.f32 "
        "{%0,%1,%2,%3},{%4,%5,%6,%7},{%8,%9},{%0,%1,%2,%3};"
        : "+f"(d[0]), "+f"(d[1]), "+f"(d[2]), "+f"(d[3])
        : "r"(a[0]), "r"(a[1]), "r"(a[2]), "r"(a[3]), "r"(b[0]), "r"(b[1]));
}
__device__ __forceinline__ void ldm_x4(uint32_t* r, uint32_t a) {
    asm volatile("ldmatrix.sync.aligned.m8n8.x4.shared.b16 {%0,%1,%2,%3}, [%4];"
                 : "=r"(r[0]), "=r"(r[1]), "=r"(r[2]), "=r"(r[3]) : "r"(a));
}
__device__ __forceinline__ void ldm_x2(uint32_t* r, uint32_t a) {
    asm volatile("ldmatrix.sync.aligned.m8n8.x2.shared.b16 {%0,%1}, [%2];"
                 : "=r"(r[0]), "=r"(r[1]) : "r"(a));
}
__device__ __forceinline__ void split_bf16(float v, __nv_bfloat16& hi,
                                           __nv_bfloat16& lo) {
    hi = __float2bfloat16_rn(v);
    lo = __float2bfloat16_rn(v - __bfloat162float(hi));
}
__device__ __forceinline__ void flag_wait(const unsigned* f, unsigned tgt) {
    if (*(volatile const unsigned*)f >= tgt) return;
    while (*(volatile const unsigned*)f < tgt) { __nanosleep(32); }
}

// ---------------- prep kernels -------------------------------------------
__global__ void wprep_rec(const float* __restrict__ g_w,
                          const float* __restrict__ a_w) {
    int idx = blockIdx.x * blockDim.x + threadIdx.x;   // NCG*32*C
    int cg = idx >> 15, r = (idx >> 10) & 31, k = idx & 1023;
    int cell = cg * CPC + (r & 15);
    const float* src = (r < 16) ? a_w : g_w;
    split_bf16(src[(size_t)cell * WROW + F + k], g_Awhi[idx], g_Awlo[idx]);
}
__global__ void xprep(const float* __restrict__ x) {
    size_t i = (size_t)blockIdx.x * blockDim.x + threadIdx.x;   // B*T*F
    split_bf16(x[i], g_xhi[i], g_xlo[i]);
}
__global__ void pwprep(const float* __restrict__ u_w,
                       const float* __restrict__ g_w,
                       const float* __restrict__ a_w) {
    int idx = blockIdx.x * blockDim.x + threadIdx.x;   // 3*C*F
    int row = idx >> 8, k = idx & 255;
    float v;
    if (row < C)           v = u_w[(size_t)row * F + k];
    else if (row < 2 * C)  v = g_w[(size_t)(row - C) * WROW + k];
    else                   v = a_w[(size_t)(row - 2 * C) * WROW + k];
    split_bf16(v, g_pwhi[idx], g_pwlo[idx]);
}
__global__ void owprep(const float* __restrict__ o_w) {
    int idx = blockIdx.x * blockDim.x + threadIdx.x;   // KOUT*C
    split_bf16(o_w[idx], g_owhi[idx], g_owlo[idx]);
}
__global__ void hinit(const float* __restrict__ h_in,
                      const float* __restrict__ s,
                      float* __restrict__ out_s) {
    int i = blockIdx.x * blockDim.x + threadIdx.x;
    if (i < BC) {
        int c = i & (C - 1);
        split_bf16(h_in[i] + tanhf(s[c]), g_hshi[i], g_hslo[i]);
    }
    if (i < C) out_s[i] = s[i];
    if (i < 16) ((unsigned*)g_flag)[i] = 0u;
}

// ---------------- generic bf16x3 GEMM bodies -----------------------------
// CTA: M=64 (A rows, hi+lo at rows+64), N=64 (B rows), K chunks of 64, 3-stage.
struct GemmFrag {
    uint32_t aoff_h[2], aoff_l[2], boff_h[2], boff_l[2];
    int wm, wn, gid, tig, lane;
};
__device__ __forceinline__ GemmFrag gemm_frag(int tid) {
    GemmFrag f;
    int warp = tid >> 5;
    f.lane = tid & 31;
    f.gid = f.lane >> 2;
    f.tig = f.lane & 3;
    f.wm = warp & 1;
    f.wn = warp >> 1;
    int aRow = ((f.lane >> 3) & 1) * 8 + (f.lane & 7);
    int aCol = ((f.lane >> 4) & 1) * 8;
    int bRow = f.lane & 7;
    int bCol = ((f.lane >> 3) & 1) * 8;
#pragma unroll
    for (int mt = 0; mt < 2; ++mt) {
        f.aoff_h[mt] = (uint32_t)((f.wm * 32 + mt * 16 + aRow) * GP + aCol) * 2;
        f.aoff_l[mt] = (uint32_t)((64 + f.wm * 32 + mt * 16 + aRow) * GP + aCol) * 2;
    }
#pragma unroll
    for (int nt = 0; nt < 2; ++nt) {
        f.boff_h[nt] = (uint32_t)((f.wn * 16 + nt * 8 + bRow) * GP + bCol) * 2;
        f.boff_l[nt] = (uint32_t)((64 + f.wn * 16 + nt * 8 + bRow) * GP + bCol) * 2;
    }
    return f;
}
__device__ __forceinline__ void gemm_load_stage(
    uint32_t sb, int stg,
    const __nv_bfloat16* __restrict__ Ahi, const __nv_bfloat16* __restrict__ Alo,
    int lda,
    const __nv_bfloat16* __restrict__ Bhi, const __nv_bfloat16* __restrict__ Blo,
    int ldb, int k0, int tid) {
    uint32_t base = sb + stg * GSTAGE;
#pragma unroll
    for (int j = 0; j < 4; ++j) {
        int g = tid + j * 256;
        int row = g >> 3, q = g & 7;
        const __nv_bfloat16* src = (row < 64)
            ? Ahi + (size_t)row * lda + k0 + q * 8
            : Alo + (size_t)(row - 64) * lda + k0 + q * 8;
        cpa16(base + (uint32_t)(row * GP + q * 8) * 2, src);
    }
#pragma unroll
    for (int j = 0; j < 4; ++j) {
        int g = tid + j * 256;
        int row = g >> 3, q = g & 7;
        const __nv_bfloat16* src = (row < 64)
            ? Bhi + (size_t)row * ldb + k0 + q * 8
            : Blo + (size_t)(row - 64) * ldb + k0 + q * 8;
        cpa16(base + GSTG + (uint32_t)(row * GP + q * 8) * 2, src);
    }
    CPA_COMMIT();
}
__device__ __forceinline__ void gemm_mma_chunk(uint32_t sb, int stg,
                                               const GemmFrag& f,
                                               float acc[2][2][4]) {
    uint32_t stA = sb + stg * GSTAGE;
    uint32_t stB = stA + GSTG;
#pragma unroll
    for (int ks = 0; ks < 4; ++ks) {
        uint32_t kk = ks * 32;                 // bytes
        uint32_t ah[2][4], al[2][4], bh[2][2], bl[2][2];
#pragma unroll
        for (int mt = 0; mt < 2; ++mt) {
            ldm_x4(ah[mt], stA + f.aoff_h[mt] + kk);
            ldm_x4(al[mt], stA + f.aoff_l[mt] + kk);
        }
#pragma unroll
        for (int nt = 0; nt < 2; ++nt) {
            ldm_x2(bh[nt], stB + f.boff_h[nt] + kk);
            ldm_x2(bl[nt], stB + f.boff_l[nt] + kk);
        }
#pragma unroll
        for (int mt = 0; mt < 2; ++mt)
#pragma unroll
            for (int nt = 0; nt < 2; ++nt) {
                mma16816(acc[mt][nt], ah[mt], bh[nt]);
                mma16816(acc[mt][nt], ah[mt], bl[nt]);
                mma16816(acc[mt][nt], al[mt], bh[nt]);
            }
    }
}
__device__ __forceinline__ void gemm_transpose(char* smem, const GemmFrag& f,
                                               float acc[2][2][4]) {
    __syncthreads();
    float* tr = (float*)smem;                  // [n 64][m 64+4]
#pragma unroll
    for (int mt = 0; mt < 2; ++mt)
#pragma unroll
        for (int nt = 0; nt < 2; ++nt)
#pragma unroll
            for (int j = 0; j < 4; ++j) {
                int n = f.wn * 16 + nt * 8 + 2 * f.tig + (j & 1);
                int m = f.wm * 32 + mt * 16 + f.gid + (j >> 1) * 8;
                tr[n * 68 + m] = acc[mt][nt][j];
            }
    __syncthreads();
}

// ---------------- pre GEMM: [U|GX|AX] = x @ W^T + bias -------------------
__global__ void __launch_bounds__(256) pre_gemm_bf16(
    const float* __restrict__ u_b, const float* __restrict__ g_b) {
    extern __shared__ char smem[];
    const uint32_t sb = smem_u32(smem);
    const int tid = threadIdx.x;
    const int n0 = blockIdx.x * 64;            // x rows
    const int m0 = blockIdx.y * 64;            // weight rows (0..3071)
    const GemmFrag f = gemm_frag(tid);

    const __nv_bfloat16* Ahi = g_pwhi + (size_t)m0 * F;
    const __nv_bfloat16* Alo = g_pwlo + (size_t)m0 * F;
    const __nv_bfloat16* Bhi = g_xhi + (size_t)n0 * F;
    const __nv_bfloat16* Blo = g_xlo + (size_t)n0 * F;

    float acc[2][2][4] = {};
    const int NC = F / 64;                     // 4 chunks
    gemm_load_stage(sb, 0, Ahi, Alo, F, Bhi, Blo, F, 0, tid);
    gemm_load_stage(sb, 1, Ahi, Alo, F, Bhi, Blo, F, 64, tid);
    gemm_load_stage(sb, 2, Ahi, Alo, F, Bhi, Blo, F, 128, tid);
#pragma unroll 1
    for (int c = 0; c < NC; ++c) {
        int pend = NC - 1 - c;
        if (pend >= 2) CPA_WAIT(2); else if (pend == 1) CPA_WAIT(1); else CPA_WAIT(0);
        __syncthreads();
        gemm_mma_chunk(sb, c % 3, f, acc);
        if (c + 3 < NC) {
            __syncthreads();
            gemm_load_stage(sb, c % 3, Ahi, Alo, F, Bhi, Blo, F, (c + 3) * 64, tid);
        }
    }
    gemm_transpose(smem, f, acc);

    const int which = m0 >> 10;
    const int cbase = m0 & 1023;
    float* dst = (which == 0) ? g_U : (which == 1) ? g_GX : g_AX;
    const float* bias = (which == 0) ? u_b : (which == 1) ? g_b : nullptr;
    const float* tr = (const float*)smem;
    const int n = tid >> 2;
    const int n_g = n0 + n;
    const int b = n_g >> 9, t = n_g & 511;     // n_g = b*T + t
    float* drow = dst + (size_t)t * BC + (size_t)b * C + cbase;
#pragma unroll
    for (int q = 0; q < 4; ++q) {
        int m = ((tid & 3) * 4 + q) * 4;
        float4 v = *(const float4*)&tr[n * 68 + m];
        if (bias) {
            float4 bv = *(const float4*)&bias[cbase + m];
            v.x += bv.x; v.y += bv.y; v.z += bv.z; v.w += bv.w;
        }
        *(float4*)&drow[m] = v;
    }
}

// ---------------- out GEMM: outs[b][t][:] = h_t @ o_w^T + o_b ------------
__global__ void __launch_bounds__(256) out_gemm_bf16(
    const float* __restrict__ o_b, float* __restrict__ outp) {
    extern __shared__ char smem[];
    const uint32_t sb = smem_u32(smem);
    const int tid = threadIdx.x;
    const int tslot = blockIdx.x;              // t: h_t stored at slot t+1
    const int m0 = blockIdx.y * 64;            // out-class rows
    const GemmFrag f = gemm_frag(tid);

    const __nv_bfloat16* Ahi = g_owhi + (size_t)m0 * C;
    const __nv_bfloat16* Alo = g_owlo + (size_t)m0 * C;
    const __nv_bfloat16* Bhi = g_hshi + (size_t)(tslot + 1) * BC;
    const __nv_bfloat16* Blo = g_hslo + (size_t)(tslot + 1) * BC;

    float acc[2][2][4] = {};
    const int NC = C / 64;                     // 16 chunks
    gemm_load_stage(sb, 0, Ahi, Alo, C, Bhi, Blo, C, 0, tid);
    gemm_load_stage(sb, 1, Ahi, Alo, C, Bhi, Blo, C, 64, tid);
    gemm_load_stage(sb, 2, Ahi, Alo, C, Bhi, Blo, C, 128, tid);
#pragma unroll 1
    for (int c = 0; c < NC; ++c) {
        int pend = NC - 1 - c;
        if (pend >= 2) CPA_WAIT(2); else if (pend == 1) CPA_WAIT(1); else CPA_WAIT(0);
        __syncthreads();
        gemm_mma_chunk(sb, c % 3, f, acc);
        if (c + 3 < NC) {
            __syncthreads();
            gemm_load_stage(sb, c % 3, Ahi, Alo, C, Bhi, Blo, C, (c + 3) * 64, tid);
        }
    }
    gemm_transpose(smem, f, acc);

    const float* tr = (const float*)smem;
    const int b = tid >> 2;                    // n index = batch
    float* drow = outp + (size_t)b * T * KOUT + (size_t)tslot * KOUT + m0;
#pragma unroll
    for (int q = 0; q < 4; ++q) {
        int m = ((tid & 3) * 4 + q) * 4;
        float4 v = *(const float4*)&tr[b * 68 + m];
        float4 bv = *(const float4*)&o_b[m0 + m];
        v.x += bv.x; v.y += bv.y; v.z += bv.z; v.w += bv.w;
        *(float4*)&drow[m] = v;
    }
}

// ---------------- recurrent chunk loader ----------------------------------
__device__ __forceinline__ void rec_load_chunk(
    int p, int s, uint32_t sb, const __nv_bfloat16* __restrict__ hhi,
    const __nv_bfloat16* __restrict__ hlo, int bbase, int tid) {
#pragma unroll
    for (int i2 = 0; i2 < 2; ++i2) {
        int i = tid + i2 * RTHR;
        int row = i >> 4, q = i & 15;
        uint32_t d0 = sb + SB_OFF(s) + (uint32_t)(row * BPITCH) * 2 + q * 16;
        const __nv_bfloat16* s0 = hhi + (size_t)(bbase + row) * C + p * 128 + q * 8;
        const __nv_bfloat16* s1 = hlo + (size_t)(bbase + row) * C + p * 128 + q * 8;
        cpa16(d0, s0);
        cpa16(d0 + B_HALF, s1);
    }
    CPA_COMMIT();
}

// ---------------- persistent recurrent kernel (flag wavefront) -----------
__global__ void __launch_bounds__(RTHR, 1) rec_kernel(
    const float* __restrict__ n_in, const float* __restrict__ d_in,
    const float* __restrict__ amax_in,
    float* __restrict__ out_n, float* __restrict__ out_d,
    float* __restrict__ out_h, float* __restrict__ out_amax) {
    extern __shared__ char smem[];
    const uint32_t sb = smem_u32(smem);
    float* red = (float*)(smem + RED_OFF);

    const int tid   = threadIdx.x;
    const int warp  = tid >> 5;
    const int lane  = tid & 31;
    const int gid   = lane >> 2;
    const int tig   = lane & 3;
    const int wn    = warp & 3;
    const int khalf = warp >> 2;
    const int cg    = blockIdx.x >> 1;
    const int bh    = blockIdx.x & 1;
    const int bbase = bh * NB;
    const int rot   = cg >> 3;                 // starting chunk = own group

    // ---- prologue: resident weights into smem ----
    for (int i = tid; i < 64 * 128; i += RTHR) {
        int row = i >> 7, q = i & 127;
        const __nv_bfloat16* src = (row < 32)
            ? g_Awhi + ((size_t)cg * 32 + row) * C + q * 8
            : g_Awlo + ((size_t)cg * 32 + row - 32) * C + q * 8;
        cpa16(sb + (uint32_t)(row * APITCH + q * 8) * 2, src);
    }
    CPA_COMMIT();

    const int aRow = ((lane >> 3) & 1) * 8 + (lane & 7);
    const int aCol = ((lane >> 4) & 1) * 8;
    const uint32_t aHi0 = sb + (uint32_t)((aRow)      * APITCH + aCol) * 2;
    const uint32_t aHi1 = sb + (uint32_t)((16 + aRow) * APITCH + aCol) * 2;
    const uint32_t aLo0 = sb + (uint32_t)((32 + aRow) * APITCH + aCol) * 2;
    const uint32_t aLo1 = sb + (uint32_t)((48 + aRow) * APITCH + aCol) * 2;
    const int bRow = wn * 8 + (lane & 7);
    const int bCol = ((lane >> 3) & 1) * 8;
    const uint32_t bOffB = (uint32_t)(bRow * BPITCH + bCol) * 2;

    float sn[4], sd[4], sa[4];
    if (khalf == 0) {
#pragma unroll
        for (int p = 0; p < 4; ++p) {
            int b  = bbase + wn * 8 + 2 * tig + (p & 1);
            int cc = cg * CPC + gid + (p >> 1) * 8;
            sn[p] = n_in[b * C + cc];
            sd[p] = d_in[b * C + cc];
            sa[p] = amax_in[b * C + cc];
        }
    }

    for (int t = 0; t < T; ++t) {
        const __nv_bfloat16* hhi = g_hshi + (size_t)t * BC;
        const __nv_bfloat16* hlo = g_hslo + (size_t)t * BC;
        const unsigned tgt = 8u * (unsigned)t;

        // early epilogue-operand prefetch (DRAM, hidden under MMA loop)
        const size_t tb = (size_t)t * BC;
        float ax[4], gx[4], ux[4];
        if (khalf == 0) {
#pragma unroll
            for (int p = 0; p < 4; ++p) {
                int b  = bbase + wn * 8 + 2 * tig + (p & 1);
                int cc = cg * CPC + gid + (p >> 1) * 8;
                size_t idx = tb + (size_t)b * C + cc;
                ax[p] = __ldg(&g_AX[idx]);
                gx[p] = __ldg(&g_GX[idx]);
                ux[p] = __ldg(&g_U[idx]);
            }
        }

        if (tid == 0) {
            flag_wait(&g_flag[bh][rot], tgt);
            flag_wait(&g_flag[bh][(rot + 1) & 7], tgt);
            __threadfence();
        }
        __syncthreads();
        rec_load_chunk(rot, 0, sb, hhi, hlo, bbase, tid);
        rec_load_chunk((rot + 1) & 7, 1, sb, hhi, hlo, bbase, tid);

        float acc[8];
#pragma unroll
        for (int q = 0; q < 8; ++q) acc[q] = 0.f;

#pragma unroll 1
        for (int i = 0; i < 8; ++i) {
            const int p = (rot + i) & 7;
            const int s = i & 1;
            if (i < 6) CPA_WAIT(1); else CPA_WAIT(0);
            __syncthreads();
            const uint32_t stg = sb + SB_OFF(s);
#pragma unroll
            for (int ks = 0; ks < 4; ++ks) {
                const int ka = p * 128 + khalf * 64 + ks * 16;
                const int kb = khalf * 64 + ks * 16;
                uint32_t ah0[4], ah1[4], al0[4], al1[4], bhf[2], blf[2];
                ldm_x4(ah0, aHi0 + ka * 2);
                ldm_x4(ah1, aHi1 + ka * 2);
                ldm_x2(bhf, stg + bOffB + kb * 2);
                ldm_x4(al0, aLo0 + ka * 2);
                ldm_x4(al1, aLo1 + ka * 2);
                ldm_x2(blf, stg + B_HALF + bOffB + kb * 2);
                mma16816(acc + 0, ah0, bhf);
                mma16816(acc + 4, ah1, bhf);
                mma16816(acc + 0, ah0, blf);
                mma16816(acc + 4, ah1, blf);
                mma16816(acc + 0, al0, bhf);
                mma16816(acc + 4, al1, bhf);
            }
            if (i < 6) {
                const int pn = (rot + i + 2) & 7;
                __syncthreads();
                if (tid == 0) {
                    flag_wait(&g_flag[bh][pn], tgt);
                    __threadfence();
                }
                __syncthreads();
                rec_load_chunk(pn, s, sb, hhi, hlo, bbase, tid);
            }
        }

        // ---- reduce + online-softmax epilogue ----
        if (khalf == 1) {
            float* dst = red + wn * 32 + lane;
#pragma unroll
            for (int q = 0; q < 8; ++q) dst[q * 128] = acc[q];
        }
        __syncthreads();
        if (khalf == 0) {
            const float* sp = red + wn * 32 + lane;
            __nv_bfloat16* whi = g_hshi + (size_t)(t + 1) * BC;
            __nv_bfloat16* wlo = g_hslo + (size_t)(t + 1) * BC;
#pragma unroll
            for (int q = 0; q < 8; ++q) acc[q] += sp[q * 128];
#pragma unroll
            for (int p = 0; p < 4; ++p) {
                int b  = bbase + wn * 8 + 2 * tig + (p & 1);
                int cc = cg * CPC + gid + (p >> 1) * 8;
                float at = acc[p] + ax[p];
                float gt = acc[4 + p] + gx[p];
                float z  = ux[p] * tanhf(gt);
                float an = fmaxf(sa[p], at);
                float ed = expf(sa[p] - an);
                float es = expf(at - an);
                sn[p] = sn[p] * ed + z * es;
                sd[p] = sd[p] * ed + es;
                float h = tanhf(sn[p] / sd[p]);
                sa[p] = an;
                __nv_bfloat16 hi, lo;
                split_bf16(h, hi, lo);
                whi[b * C + cc] = hi;
                wlo[b * C + cc] = lo;
            }
        }
        __threadfence();
        __syncthreads();
        if (tid == 0) atomicAdd(&g_flag[bh][rot], 1u);
    }

    if (khalf == 0) {
#pragma unroll
        for (int p = 0; p < 4; ++p) {
            int b  = bbase + wn * 8 + 2 * tig + (p & 1);
            int cc = cg * CPC + gid + (p >> 1) * 8;
            out_n[b * C + cc]    = sn[p];
            out_d[b * C + cc]    = sd[p];
            out_h[b * C + cc]    = tanhf(sn[p] / sd[p]);
            out_amax[b * C + cc] = sa[p];
        }
    }
}

// ---------------- launch ---------------------------------------------------
extern "C" void kernel_launch(void* const* d_in, const int* in_sizes, int n_in,
                              void* d_out, int out_size) {
    (void)in_sizes; (void)n_in; (void)out_size;
    const float* x      = (const float*)d_in[0];
    const float* s      = (const float*)d_in[1];
    const float* n0     = (const float*)d_in[2];
    const float* d0     = (const float*)d_in[3];
    const float* h0     = (const float*)d_in[4];
    const float* amax0  = (const float*)d_in[5];
    const float* u_w    = (const float*)d_in[6];
    const float* u_b    = (const float*)d_in[7];
    const float* g_w    = (const float*)d_in[8];
    const float* g_b    = (const float*)d_in[9];
    const float* a_w    = (const float*)d_in[10];
    const float* o_w    = (const float*)d_in[11];
    const float* o_b    = (const float*)d_in[12];

    float* out        = (float*)d_out;
    float* out_outs   = out;
    float* out_s      = out + (size_t)B * T * KOUT;
    float* out_n      = out_s + C;
    float* out_d      = out_n + (size_t)B * C;
    float* out_h      = out_d + (size_t)B * C;
    float* out_amax   = out_h + (size_t)B * C;

    cudaFuncSetAttribute(rec_kernel, cudaFuncAttributeMaxDynamicSharedMemorySize, RSMEM);
    cudaFuncSetAttribute(pre_gemm_bf16, cudaFuncAttributeMaxDynamicSharedMemorySize, GSMEM);
    cudaFuncSetAttribute(out_gemm_bf16, cudaFuncAttributeMaxDynamicSharedMemorySize, GSMEM);

    wprep_rec<<<NCG * 32 * C / 256, 256>>>(g_w, a_w);
    xprep<<<(B * T * F) / 256, 256>>>(x);
    pwprep<<<(3 * C * F) / 256, 256>>>(u_w, g_w, a_w);
    owprep<<<(KOUT * C) / 256, 256>>>(o_w);
    hinit<<<(BC + 255) / 256, 256>>>(h0, s, out_s);
    pre_gemm_bf16<<<dim3(512, 48), 256, GSMEM>>>(u_b, g_b);
    rec_kernel<<<RCTA, RTHR, RSMEM>>>(n0, d0, amax0,
                                      out_n, out_d, out_h, out_amax);
    out_gemm_bf16<<<dim3(512, 4), 256, GSMEM>>>(o_b, out_outs);
}

// round 7
// speedup vs baseline: 1.3152x; 1.3152x over previous
#include <cuda_runtime.h>
#include <cuda_bf16.h>
#include <cstdint>

#define B 64
#define T 512
#define F 256
#define C 1024
#define KOUT 256
#define BC (B * C)
#define WROW (F + C)          // 1280 floats per g_w/a_w row

// ---------------- recurrent kernel config --------------------------------
#define RCTA 128              // (cg 0..63) x (batch-half 0..1)
#define NCG  64               // cell groups
#define RTHR 256
#define CPC  16               // cells per CTA  (A tile M = 32 = 16 a + 16 g)
#define NB   32               // batches per CTA
#define APITCH 1032           // smem A pitch (bf16)
#define BPITCH 136            // smem B pitch (bf16)
#define A_BYTES (64 * APITCH * 2)              // rows 0-31 hi, 32-63 lo
#define B_HALF  (NB * BPITCH * 2)              // 8704 per hi or lo tile
#define B_STAGE (2 * B_HALF)                   // 17408
#define NSTG 3
#define SB_OFF(s) (A_BYTES + (s) * B_STAGE)
#define RED_OFF (A_BYTES + NSTG * B_STAGE)     // 184320
#define RSMEM (RED_OFF + 4096)                 // 188416

// ---------------- bf16 GEMM (pre/out) config -----------------------------
#define GP 72                                   // smem pitch (bf16)
#define GSTG (128 * GP * 2)                     // 18432 B per operand stage
#define GSTAGE (2 * GSTG)                       // 36864
#define GSMEM (3 * GSTAGE)                      // 110592

// ---------------- device scratch -----------------------------------------
__device__ __align__(16) float g_U [(size_t)T * BC];
__device__ __align__(16) float g_GX[(size_t)T * BC];
__device__ __align__(16) float g_AX[(size_t)T * BC];
__device__ __align__(16) __nv_bfloat16 g_hshi[(size_t)(T + 1) * BC]; // h slots
__device__ __align__(16) __nv_bfloat16 g_hslo[(size_t)(T + 1) * BC];
__device__ __align__(16) __nv_bfloat16 g_Awhi[NCG * 32 * C];  // rec weights
__device__ __align__(16) __nv_bfloat16 g_Awlo[NCG * 32 * C];
__device__ __align__(16) __nv_bfloat16 g_xhi[(size_t)B * T * F];
__device__ __align__(16) __nv_bfloat16 g_xlo[(size_t)B * T * F];
__device__ __align__(16) __nv_bfloat16 g_pwhi[3 * C * F];     // u/gF/aF rows
__device__ __align__(16) __nv_bfloat16 g_pwlo[3 * C * F];
__device__ __align__(16) __nv_bfloat16 g_owhi[KOUT * C];
__device__ __align__(16) __nv_bfloat16 g_owlo[KOUT * C];
__device__ unsigned g_flag[2][8];

// ---------------- helpers -------------------------------------------------
__device__ __forceinline__ uint32_t smem_u32(const void* p) {
    uint32_t a;
    asm("{ .reg .u64 t; cvta.to.shared.u64 t, %1; cvt.u32.u64 %0, t; }"
        : "=r"(a) : "l"(p));
    return a;
}
__device__ __forceinline__ void cpa16(uint32_t dst, const void* src) {
    asm volatile("cp.async.cg.shared.global [%0], [%1], 16;"
                 :: "r"(dst), "l"(src) : "memory");
}
#define CPA_COMMIT() asm volatile("cp.async.commit_group;" ::: "memory")
#define CPA_WAIT(n)  asm volatile("cp.async.wait_group %0;" :: "n"(n) : "memory")

__device__ __forceinline__ void mma16816(float* d, const uint32_t* a,
                                         const uint32_t* b) {
    asm volatile(
        "mma.sync.aligned.m16n8k16.row.col.f32.bf16.bf16.f32 "
        "{%0,%1,%2,%3},{%4,%5,%6,%7},{%8,%9},{%0,%1,%2,%3};"
        : "+f"(d[0]), "+f"(d[1]), "+f"(d[2]), "+f"(d[3])
        : "r"(a[0]), "r"(a[1]), "r"(a[2]), "r"(a[3]), "r"(b[0]), "r"(b[1]));
}
__device__ __forceinline__ void ldm_x4(uint32_t* r, uint32_t a) {
    asm volatile("ldmatrix.sync.aligned.m8n8.x4.shared.b16 {%0,%1,%2,%3}, [%4];"
                 : "=r"(r[0]), "=r"(r[1]), "=r"(r[2]), "=r"(r[3]) : "r"(a));
}
__device__ __forceinline__ void ldm_x2(uint32_t* r, uint32_t a) {
    asm volatile("ldmatrix.sync.aligned.m8n8.x2.shared.b16 {%0,%1}, [%2];"
                 : "=r"(r[0]), "=r"(r[1]) : "r"(a));
}
__device__ __forceinline__ void split_bf16(float v, __nv_bfloat16& hi,
                                           __nv_bfloat16& lo) {
    hi = __float2bfloat16_rn(v);
    lo = __float2bfloat16_rn(v - __bfloat162float(hi));
}
__device__ __forceinline__ void flag_wait(const unsigned* f, unsigned tgt) {
    if (*(volatile const unsigned*)f >= tgt) return;
    while (*(volatile const unsigned*)f < tgt) { __nanosleep(32); }
}

// ---------------- prep kernels -------------------------------------------
__global__ void wprep_rec(const float* __restrict__ g_w,
                          const float* __restrict__ a_w) {
    int idx = blockIdx.x * blockDim.x + threadIdx.x;   // NCG*32*C
    int cg = idx >> 15, r = (idx >> 10) & 31, k = idx & 1023;
    int cell = cg * CPC + (r & 15);
    const float* src = (r < 16) ? a_w : g_w;
    split_bf16(src[(size_t)cell * WROW + F + k], g_Awhi[idx], g_Awlo[idx]);
}
__global__ void xprep(const float* __restrict__ x) {
    size_t i = (size_t)blockIdx.x * blockDim.x + threadIdx.x;   // B*T*F
    split_bf16(x[i], g_xhi[i], g_xlo[i]);
}
__global__ void pwprep(const float* __restrict__ u_w,
                       const float* __restrict__ g_w,
                       const float* __restrict__ a_w) {
    int idx = blockIdx.x * blockDim.x + threadIdx.x;   // 3*C*F
    int row = idx >> 8, k = idx & 255;
    float v;
    if (row < C)           v = u_w[(size_t)row * F + k];
    else if (row < 2 * C)  v = g_w[(size_t)(row - C) * WROW + k];
    else                   v = a_w[(size_t)(row - 2 * C) * WROW + k];
    split_bf16(v, g_pwhi[idx], g_pwlo[idx]);
}
__global__ void owprep(const float* __restrict__ o_w) {
    int idx = blockIdx.x * blockDim.x + threadIdx.x;   // KOUT*C
    split_bf16(o_w[idx], g_owhi[idx], g_owlo[idx]);
}
__global__ void hinit(const float* __restrict__ h_in,
                      const float* __restrict__ s,
                      float* __restrict__ out_s) {
    int i = blockIdx.x * blockDim.x + threadIdx.x;
    if (i < BC) {
        int c = i & (C - 1);
        split_bf16(h_in[i] + tanhf(s[c]), g_hshi[i], g_hslo[i]);
    }
    if (i < C) out_s[i] = s[i];
    if (i < 16) ((unsigned*)g_flag)[i] = 0u;
}

// ---------------- generic bf16x3 GEMM bodies -----------------------------
struct GemmFrag {
    uint32_t aoff_h[2], aoff_l[2], boff_h[2], boff_l[2];
    int wm, wn, gid, tig, lane;
};
__device__ __forceinline__ GemmFrag gemm_frag(int tid) {
    GemmFrag f;
    int warp = tid >> 5;
    f.lane = tid & 31;
    f.gid = f.lane >> 2;
    f.tig = f.lane & 3;
    f.wm = warp & 1;
    f.wn = warp >> 1;
    int aRow = ((f.lane >> 3) & 1) * 8 + (f.lane & 7);
    int aCol = ((f.lane >> 4) & 1) * 8;
    int bRow = f.lane & 7;
    int bCol = ((f.lane >> 3) & 1) * 8;
#pragma unroll
    for (int mt = 0; mt < 2; ++mt) {
        f.aoff_h[mt] = (uint32_t)((f.wm * 32 + mt * 16 + aRow) * GP + aCol) * 2;
        f.aoff_l[mt] = (uint32_t)((64 + f.wm * 32 + mt * 16 + aRow) * GP + aCol) * 2;
    }
#pragma unroll
    for (int nt = 0; nt < 2; ++nt) {
        f.boff_h[nt] = (uint32_t)((f.wn * 16 + nt * 8 + bRow) * GP + bCol) * 2;
        f.boff_l[nt] = (uint32_t)((64 + f.wn * 16 + nt * 8 + bRow) * GP + bCol) * 2;
    }
    return f;
}
__device__ __forceinline__ void gemm_load_stage(
    uint32_t sb, int stg,
    const __nv_bfloat16* __restrict__ Ahi, const __nv_bfloat16* __restrict__ Alo,
    int lda,
    const __nv_bfloat16* __restrict__ Bhi, const __nv_bfloat16* __restrict__ Blo,
    int ldb, int k0, int tid) {
    uint32_t base = sb + stg * GSTAGE;
#pragma unroll
    for (int j = 0; j < 4; ++j) {
        int g = tid + j * 256;
        int row = g >> 3, q = g & 7;
        const __nv_bfloat16* src = (row < 64)
            ? Ahi + (size_t)row * lda + k0 + q * 8
            : Alo + (size_t)(row - 64) * lda + k0 + q * 8;
        cpa16(base + (uint32_t)(row * GP + q * 8) * 2, src);
    }
#pragma unroll
    for (int j = 0; j < 4; ++j) {
        int g = tid + j * 256;
        int row = g >> 3, q = g & 7;
        const __nv_bfloat16* src = (row < 64)
            ? Bhi + (size_t)row * ldb + k0 + q * 8
            : Blo + (size_t)(row - 64) * ldb + k0 + q * 8;
        cpa16(base + GSTG + (uint32_t)(row * GP + q * 8) * 2, src);
    }
    CPA_COMMIT();
}
__device__ __forceinline__ void gemm_mma_chunk(uint32_t sb, int stg,
                                               const GemmFrag& f,
                                               float acc[2][2][4]) {
    uint32_t stA = sb + stg * GSTAGE;
    uint32_t stB = stA + GSTG;
#pragma unroll
    for (int ks = 0; ks < 4; ++ks) {
        uint32_t kk = ks * 32;                 // bytes
        uint32_t ah[2][4], al[2][4], bh[2][2], bl[2][2];
#pragma unroll
        for (int mt = 0; mt < 2; ++mt) {
            ldm_x4(ah[mt], stA + f.aoff_h[mt] + kk);
            ldm_x4(al[mt], stA + f.aoff_l[mt] + kk);
        }
#pragma unroll
        for (int nt = 0; nt < 2; ++nt) {
            ldm_x2(bh[nt], stB + f.boff_h[nt] + kk);
            ldm_x2(bl[nt], stB + f.boff_l[nt] + kk);
        }
#pragma unroll
        for (int mt = 0; mt < 2; ++mt)
#pragma unroll
            for (int nt = 0; nt < 2; ++nt) {
                mma16816(acc[mt][nt], ah[mt], bh[nt]);
                mma16816(acc[mt][nt], ah[mt], bl[nt]);
                mma16816(acc[mt][nt], al[mt], bh[nt]);
            }
    }
}
__device__ __forceinline__ void gemm_transpose(char* smem, const GemmFrag& f,
                                               float acc[2][2][4]) {
    __syncthreads();
    float* tr = (float*)smem;                  // [n 64][m 64+4]
#pragma unroll
    for (int mt = 0; mt < 2; ++mt)
#pragma unroll
        for (int nt = 0; nt < 2; ++nt)
#pragma unroll
            for (int j = 0; j < 4; ++j) {
                int n = f.wn * 16 + nt * 8 + 2 * f.tig + (j & 1);
                int m = f.wm * 32 + mt * 16 + f.gid + (j >> 1) * 8;
                tr[n * 68 + m] = acc[mt][nt][j];
            }
    __syncthreads();
}

// ---------------- pre GEMM: [U|GX|AX] = x @ W^T + bias -------------------
__global__ void __launch_bounds__(256) pre_gemm_bf16(
    const float* __restrict__ u_b, const float* __restrict__ g_b) {
    extern __shared__ char smem[];
    const uint32_t sb = smem_u32(smem);
    const int tid = threadIdx.x;
    const int n0 = blockIdx.x * 64;            // x rows
    const int m0 = blockIdx.y * 64;            // weight rows (0..3071)
    const GemmFrag f = gemm_frag(tid);

    const __nv_bfloat16* Ahi = g_pwhi + (size_t)m0 * F;
    const __nv_bfloat16* Alo = g_pwlo + (size_t)m0 * F;
    const __nv_bfloat16* Bhi = g_xhi + (size_t)n0 * F;
    const __nv_bfloat16* Blo = g_xlo + (size_t)n0 * F;

    float acc[2][2][4] = {};
    const int NC = F / 64;                     // 4 chunks
    gemm_load_stage(sb, 0, Ahi, Alo, F, Bhi, Blo, F, 0, tid);
    gemm_load_stage(sb, 1, Ahi, Alo, F, Bhi, Blo, F, 64, tid);
    gemm_load_stage(sb, 2, Ahi, Alo, F, Bhi, Blo, F, 128, tid);
#pragma unroll 1
    for (int c = 0; c < NC; ++c) {
        int pend = NC - 1 - c;
        if (pend >= 2) CPA_WAIT(2); else if (pend == 1) CPA_WAIT(1); else CPA_WAIT(0);
        __syncthreads();
        gemm_mma_chunk(sb, c % 3, f, acc);
        if (c + 3 < NC) {
            __syncthreads();
            gemm_load_stage(sb, c % 3, Ahi, Alo, F, Bhi, Blo, F, (c + 3) * 64, tid);
        }
    }
    gemm_transpose(smem, f, acc);

    const int which = m0 >> 10;
    const int cbase = m0 & 1023;
    float* dst = (which == 0) ? g_U : (which == 1) ? g_GX : g_AX;
    const float* bias = (which == 0) ? u_b : (which == 1) ? g_b : nullptr;
    const float* tr = (const float*)smem;
    const int n = tid >> 2;
    const int n_g = n0 + n;
    const int b = n_g >> 9, t = n_g & 511;     // n_g = b*T + t
    float* drow = dst + (size_t)t * BC + (size_t)b * C + cbase;
#pragma unroll
    for (int q = 0; q < 4; ++q) {
        int m = ((tid & 3) * 4 + q) * 4;
        float4 v = *(const float4*)&tr[n * 68 + m];
        if (bias) {
            float4 bv = *(const float4*)&bias[cbase + m];
            v.x += bv.x; v.y += bv.y; v.z += bv.z; v.w += bv.w;
        }
        *(float4*)&drow[m] = v;
    }
}

// ---------------- out GEMM: outs[b][t][:] = h_t @ o_w^T + o_b ------------
__global__ void __launch_bounds__(256) out_gemm_bf16(
    const float* __restrict__ o_b, float* __restrict__ outp) {
    extern __shared__ char smem[];
    const uint32_t sb = smem_u32(smem);
    const int tid = threadIdx.x;
    const int tslot = blockIdx.x;              // t: h_t stored at slot t+1
    const int m0 = blockIdx.y * 64;            // out-class rows
    const GemmFrag f = gemm_frag(tid);

    const __nv_bfloat16* Ahi = g_owhi + (size_t)m0 * C;
    const __nv_bfloat16* Alo = g_owlo + (size_t)m0 * C;
    const __nv_bfloat16* Bhi = g_hshi + (size_t)(tslot + 1) * BC;
    const __nv_bfloat16* Blo = g_hslo + (size_t)(tslot + 1) * BC;

    float acc[2][2][4] = {};
    const int NC = C / 64;                     // 16 chunks
    gemm_load_stage(sb, 0, Ahi, Alo, C, Bhi, Blo, C, 0, tid);
    gemm_load_stage(sb, 1, Ahi, Alo, C, Bhi, Blo, C, 64, tid);
    gemm_load_stage(sb, 2, Ahi, Alo, C, Bhi, Blo, C, 128, tid);
#pragma unroll 1
    for (int c = 0; c < NC; ++c) {
        int pend = NC - 1 - c;
        if (pend >= 2) CPA_WAIT(2); else if (pend == 1) CPA_WAIT(1); else CPA_WAIT(0);
        __syncthreads();
        gemm_mma_chunk(sb, c % 3, f, acc);
        if (c + 3 < NC) {
            __syncthreads();
            gemm_load_stage(sb, c % 3, Ahi, Alo, C, Bhi, Blo, C, (c + 3) * 64, tid);
        }
    }
    gemm_transpose(smem, f, acc);

    const float* tr = (const float*)smem;
    const int b = tid >> 2;                    // n index = batch
    float* drow = outp + (size_t)b * T * KOUT + (size_t)tslot * KOUT + m0;
#pragma unroll
    for (int q = 0; q < 4; ++q) {
        int m = ((tid & 3) * 4 + q) * 4;
        float4 v = *(const float4*)&tr[b * 68 + m];
        float4 bv = *(const float4*)&o_b[m0 + m];
        v.x += bv.x; v.y += bv.y; v.z += bv.z; v.w += bv.w;
        *(float4*)&drow[m] = v;
    }
}

// ---------------- recurrent chunk loader ----------------------------------
__device__ __forceinline__ void rec_load_chunk(
    int p, int s, uint32_t sb, const __nv_bfloat16* __restrict__ hhi,
    const __nv_bfloat16* __restrict__ hlo, int bbase, int tid) {
#pragma unroll
    for (int i2 = 0; i2 < 2; ++i2) {
        int i = tid + i2 * RTHR;
        int row = i >> 4, q = i & 15;
        uint32_t d0 = sb + SB_OFF(s) + (uint32_t)(row * BPITCH) * 2 + q * 16;
        const __nv_bfloat16* s0 = hhi + (size_t)(bbase + row) * C + p * 128 + q * 8;
        const __nv_bfloat16* s1 = hlo + (size_t)(bbase + row) * C + p * 128 + q * 8;
        cpa16(d0, s0);
        cpa16(d0 + B_HALF, s1);
    }
    CPA_COMMIT();
}

// ---------------- persistent recurrent kernel ----------------------------
// One flag-wait per step; 3-stage cp.async pipeline; 1 syncthreads/chunk.
__global__ void __launch_bounds__(RTHR, 1) rec_kernel(
    const float* __restrict__ n_in, const float* __restrict__ d_in,
    const float* __restrict__ amax_in,
    float* __restrict__ out_n, float* __restrict__ out_d,
    float* __restrict__ out_h, float* __restrict__ out_amax) {
    extern __shared__ char smem[];
    const uint32_t sb = smem_u32(smem);
    float* red = (float*)(smem + RED_OFF);

    const int tid   = threadIdx.x;
    const int warp  = tid >> 5;
    const int lane  = tid & 31;
    const int gid   = lane >> 2;
    const int tig   = lane & 3;
    const int wn    = warp & 3;
    const int khalf = warp >> 2;
    const int cg    = blockIdx.x >> 1;
    const int bh    = blockIdx.x & 1;
    const int bbase = bh * NB;
    const int rot   = cg >> 3;                 // starting chunk = own group

    // ---- prologue: resident weights into smem ----
    for (int i = tid; i < 64 * 128; i += RTHR) {
        int row = i >> 7, q = i & 127;
        const __nv_bfloat16* src = (row < 32)
            ? g_Awhi + ((size_t)cg * 32 + row) * C + q * 8
            : g_Awlo + ((size_t)cg * 32 + row - 32) * C + q * 8;
        cpa16(sb + (uint32_t)(row * APITCH + q * 8) * 2, src);
    }
    CPA_COMMIT();

    const int aRow = ((lane >> 3) & 1) * 8 + (lane & 7);
    const int aCol = ((lane >> 4) & 1) * 8;
    const uint32_t aHi0 = sb + (uint32_t)((aRow)      * APITCH + aCol) * 2;
    const uint32_t aHi1 = sb + (uint32_t)((16 + aRow) * APITCH + aCol) * 2;
    const uint32_t aLo0 = sb + (uint32_t)((32 + aRow) * APITCH + aCol) * 2;
    const uint32_t aLo1 = sb + (uint32_t)((48 + aRow) * APITCH + aCol) * 2;
    const int bRow = wn * 8 + (lane & 7);
    const int bCol = ((lane >> 3) & 1) * 8;
    const uint32_t bOffB = (uint32_t)(bRow * BPITCH + bCol) * 2;

    float sn[4], sd[4], sa[4];
    if (khalf == 0) {
#pragma unroll
        for (int p = 0; p < 4; ++p) {
            int b  = bbase + wn * 8 + 2 * tig + (p & 1);
            int cc = cg * CPC + gid + (p >> 1) * 8;
            sn[p] = n_in[b * C + cc];
            sd[p] = d_in[b * C + cc];
            sa[p] = amax_in[b * C + cc];
        }
    }

    for (int t = 0; t < T; ++t) {
        const __nv_bfloat16* hhi = g_hshi + (size_t)t * BC;
        const __nv_bfloat16* hlo = g_hslo + (size_t)t * BC;
        const unsigned tgt = 8u * (unsigned)t;

        // early epilogue-operand prefetch (DRAM, hidden under MMA loop)
        const size_t tb = (size_t)t * BC;
        float ax[4], gx[4], ux[4];
        if (khalf == 0) {
#pragma unroll
            for (int p = 0; p < 4; ++p) {
                int b  = bbase + wn * 8 + 2 * tig + (p & 1);
                int cc = cg * CPC + gid + (p >> 1) * 8;
                size_t idx = tb + (size_t)b * C + cc;
                ax[p] = __ldg(&g_AX[idx]);
                gx[p] = __ldg(&g_GX[idx]);
                ux[p] = __ldg(&g_U[idx]);
            }
        }

        // ---- single wait point: all 8 producer groups of step t-1 done ----
        if (tid == 0) {
#pragma unroll
            for (int g = 0; g < 8; ++g) flag_wait(&g_flag[bh][g], tgt);
            __threadfence();
        }
        __syncthreads();
        rec_load_chunk(rot, 0, sb, hhi, hlo, bbase, tid);
        rec_load_chunk((rot + 1) & 7, 1, sb, hhi, hlo, bbase, tid);

        float acc[8];
#pragma unroll
        for (int q = 0; q < 8; ++q) acc[q] = 0.f;

#pragma unroll 1
        for (int i = 0; i < 8; ++i) {
            const int p = (rot + i) & 7;
            if (i < 7) CPA_WAIT(1); else CPA_WAIT(0);
            __syncthreads();                  // stage (i+2)%3 free: consumed at i-1
            if (i < 6)
                rec_load_chunk((rot + i + 2) & 7, (i + 2) % NSTG, sb, hhi, hlo,
                               bbase, tid);
            const uint32_t stg = sb + SB_OFF(i % NSTG);
#pragma unroll
            for (int ks = 0; ks < 4; ++ks) {
                const int ka = p * 128 + khalf * 64 + ks * 16;
                const int kb = khalf * 64 + ks * 16;
                uint32_t ah0[4], ah1[4], al0[4], al1[4], bhf[2], blf[2];
                ldm_x4(ah0, aHi0 + ka * 2);
                ldm_x4(ah1, aHi1 + ka * 2);
                ldm_x2(bhf, stg + bOffB + kb * 2);
                ldm_x4(al0, aLo0 + ka * 2);
                ldm_x4(al1, aLo1 + ka * 2);
                ldm_x2(blf, stg + B_HALF + bOffB + kb * 2);
                mma16816(acc + 0, ah0, bhf);
                mma16816(acc + 4, ah1, bhf);
                mma16816(acc + 0, ah0, blf);
                mma16816(acc + 4, ah1, blf);
                mma16816(acc + 0, al0, bhf);
                mma16816(acc + 4, al1, bhf);
            }
        }

        // ---- reduce + online-softmax epilogue ----
        if (khalf == 1) {
            float* dst = red + wn * 32 + lane;
#pragma unroll
            for (int q = 0; q < 8; ++q) dst[q * 128] = acc[q];
        }
        __syncthreads();
        if (khalf == 0) {
            const float* sp = red + wn * 32 + lane;
            __nv_bfloat16* whi = g_hshi + (size_t)(t + 1) * BC;
            __nv_bfloat16* wlo = g_hslo + (size_t)(t + 1) * BC;
#pragma unroll
            for (int q = 0; q < 8; ++q) acc[q] += sp[q * 128];
#pragma unroll
            for (int p = 0; p < 4; ++p) {
                int b  = bbase + wn * 8 + 2 * tig + (p & 1);
                int cc = cg * CPC + gid + (p >> 1) * 8;
                float at = acc[p] + ax[p];
                float gt = acc[4 + p] + gx[p];
                float z  = ux[p] * tanhf(gt);
                float an = fmaxf(sa[p], at);
                float ed = expf(sa[p] - an);
                float es = expf(at - an);
                sn[p] = sn[p] * ed + z * es;
                sd[p] = sd[p] * ed + es;
                float h = tanhf(sn[p] / sd[p]);
                sa[p] = an;
                __nv_bfloat16 hi, lo;
                split_bf16(h, hi, lo);
                whi[b * C + cc] = hi;
                wlo[b * C + cc] = lo;
            }
        }
        __threadfence();
        __syncthreads();
        if (tid == 0) atomicAdd(&g_flag[bh][rot], 1u);
    }

    if (khalf == 0) {
#pragma unroll
        for (int p = 0; p < 4; ++p) {
            int b  = bbase + wn * 8 + 2 * tig + (p & 1);
            int cc = cg * CPC + gid + (p >> 1) * 8;
            out_n[b * C + cc]    = sn[p];
            out_d[b * C + cc]    = sd[p];
            out_h[b * C + cc]    = tanhf(sn[p] / sd[p]);
            out_amax[b * C + cc] = sa[p];
        }
    }
}

// ---------------- launch ---------------------------------------------------
extern "C" void kernel_launch(void* const* d_in, const int* in_sizes, int n_in,
                              void* d_out, int out_size) {
    (void)in_sizes; (void)n_in; (void)out_size;
    const float* x      = (const float*)d_in[0];
    const float* s      = (const float*)d_in[1];
    const float* n0     = (const float*)d_in[2];
    const float* d0     = (const float*)d_in[3];
    const float* h0     = (const float*)d_in[4];
    const float* amax0  = (const float*)d_in[5];
    const float* u_w    = (const float*)d_in[6];
    const float* u_b    = (const float*)d_in[7];
    const float* g_w    = (const float*)d_in[8];
    const float* g_b    = (const float*)d_in[9];
    const float* a_w    = (const float*)d_in[10];
    const float* o_w    = (const float*)d_in[11];
    const float* o_b    = (const float*)d_in[12];

    float* out        = (float*)d_out;
    float* out_outs   = out;
    float* out_s      = out + (size_t)B * T * KOUT;
    float* out_n      = out_s + C;
    float* out_d      = out_n + (size_t)B * C;
    float* out_h      = out_d + (size_t)B * C;
    float* out_amax   = out_h + (size_t)B * C;

    cudaFuncSetAttribute(rec_kernel, cudaFuncAttributeMaxDynamicSharedMemorySize, RSMEM);
    cudaFuncSetAttribute(pre_gemm_bf16, cudaFuncAttributeMaxDynamicSharedMemorySize, GSMEM);
    cudaFuncSetAttribute(out_gemm_bf16, cudaFuncAttributeMaxDynamicSharedMemorySize, GSMEM);

    wprep_rec<<<NCG * 32 * C / 256, 256>>>(g_w, a_w);
    xprep<<<(B * T * F) / 256, 256>>>(x);
    pwprep<<<(3 * C * F) / 256, 256>>>(u_w, g_w, a_w);
    owprep<<<(KOUT * C) / 256, 256>>>(o_w);
    hinit<<<(BC + 255) / 256, 256>>>(h0, s, out_s);
    pre_gemm_bf16<<<dim3(512, 48), 256, GSMEM>>>(u_b, g_b);
    rec_kernel<<<RCTA, RTHR, RSMEM>>>(n0, d0, amax0,
                                      out_n, out_d, out_h, out_amax);
    out_gemm_bf16<<<dim3(512, 4), 256, GSMEM>>>(o_b, out_outs);
}

// round 9
// speedup vs baseline: 1.4262x; 1.0844x over previous
#include <cuda_runtime.h>
#include <cuda_bf16.h>
#include <cstdint>

#define B 64
#define T 512
#define F 256
#define C 1024
#define KOUT 256
#define BC (B * C)
#define WROW (F + C)          // 1280 floats per g_w/a_w row

// ---------------- recurrent kernel config --------------------------------
#define RCTA 128              // (cg 0..63) x (batch-half 0..1)
#define NCG  64               // cell groups
#define RTHR 512              // 16 warps: kq = warp>>2, wn = warp&3
#define CPC  16               // cells per CTA  (A tile M = 32 = 16 a + 16 g)
#define NB   32               // batches per CTA
#define APITCH 1032           // smem A pitch (bf16)
#define BPITCH 136            // smem B pitch (bf16)
#define A_BYTES (64 * APITCH * 2)              // rows 0-31 hi, 32-63 lo
#define B_HALF  (NB * BPITCH * 2)              // 8704 per hi or lo tile
#define B_STAGE (2 * B_HALF)                   // 17408
#define NSTG 3
#define SB_OFF(s) (A_BYTES + (s) * B_STAGE)
#define RED_OFF (A_BYTES + NSTG * B_STAGE)     // 184320
#define RSMEM (RED_OFF + 12288)                // 196608 (3x1024 floats reduce)

// ---------------- bf16 GEMM (pre/out) config -----------------------------
#define GP 72                                   // smem pitch (bf16)
#define GSTG (128 * GP * 2)                     // 18432 B per operand stage
#define GSTAGE (2 * GSTG)                       // 36864
#define GSMEM (3 * GSTAGE)                      // 110592

// ---------------- device scratch -----------------------------------------
__device__ __align__(16) float g_U [(size_t)T * BC];
__device__ __align__(16) float g_GX[(size_t)T * BC];
__device__ __align__(16) float g_AX[(size_t)T * BC];
__device__ __align__(16) __nv_bfloat16 g_hshi[(size_t)(T + 1) * BC]; // h slots
__device__ __align__(16) __nv_bfloat16 g_hslo[(size_t)(T + 1) * BC];
__device__ __align__(16) __nv_bfloat16 g_Awhi[NCG * 32 * C];  // rec weights
__device__ __align__(16) __nv_bfloat16 g_Awlo[NCG * 32 * C];
__device__ __align__(16) __nv_bfloat16 g_xhi[(size_t)B * T * F];
__device__ __align__(16) __nv_bfloat16 g_xlo[(size_t)B * T * F];
__device__ __align__(16) __nv_bfloat16 g_pwhi[3 * C * F];     // u/gF/aF rows
__device__ __align__(16) __nv_bfloat16 g_pwlo[3 * C * F];
__device__ __align__(16) __nv_bfloat16 g_owhi[KOUT * C];
__device__ __align__(16) __nv_bfloat16 g_owlo[KOUT * C];
__device__ __align__(32) unsigned g_flag[2][8];

// ---------------- helpers -------------------------------------------------
__device__ __forceinline__ uint32_t smem_u32(const void* p) {
    uint32_t a;
    asm("{ .reg .u64 t; cvta.to.shared.u64 t, %1; cvt.u32.u64 %0, t; }"
        : "=r"(a) : "l"(p));
    return a;
}
__device__ __forceinline__ void cpa16(uint32_t dst, const void* src) {
    asm volatile("cp.async.cg.shared.global [%0], [%1], 16;"
                 :: "r"(dst), "l"(src) : "memory");
}
#define CPA_COMMIT() asm volatile("cp.async.commit_group;" ::: "memory")
#define CPA_WAIT(n)  asm volatile("cp.async.wait_group %0;" :: "n"(n) : "memory")

__device__ __forceinline__ void mma16816(float* d, const uint32_t* a,
                                         const uint32_t* b) {
    asm volatile(
        "mma.sync.aligned.m16n8k16.row.col.f32.bf16.bf16.f32 "
        "{%0,%1,%2,%3},{%4,%5,%6,%7},{%8,%9},{%0,%1,%2,%3};"
        : "+f"(d[0]), "+f"(d[1]), "+f"(d[2]), "+f"(d[3])
        : "r"(a[0]), "r"(a[1]), "r"(a[2]), "r"(a[3]), "r"(b[0]), "r"(b[1]));
}
__device__ __forceinline__ void ldm_x4(uint32_t* r, uint32_t a) {
    asm volatile("ldmatrix.sync.aligned.m8n8.x4.shared.b16 {%0,%1,%2,%3}, [%4];"
                 : "=r"(r[0]), "=r"(r[1]), "=r"(r[2]), "=r"(r[3]) : "r"(a));
}
__device__ __forceinline__ void ldm_x2(uint32_t* r, uint32_t a) {
    asm volatile("ldmatrix.sync.aligned.m8n8.x2.shared.b16 {%0,%1}, [%2];"
                 : "=r"(r[0]), "=r"(r[1]) : "r"(a));
}
__device__ __forceinline__ void split_bf16(float v, __nv_bfloat16& hi,
                                           __nv_bfloat16& lo) {
    hi = __float2bfloat16_rn(v);
    lo = __float2bfloat16_rn(v - __bfloat162float(hi));
}
// poll all 8 producer flags with two volatile v4 loads (one L2 round trip)
__device__ __forceinline__ void flag_wait8(const unsigned* f, unsigned tgt) {
    for (;;) {
        unsigned a0, a1, a2, a3, b0, b1, b2, b3;
        asm volatile("ld.volatile.global.v4.u32 {%0,%1,%2,%3}, [%4];"
                     : "=r"(a0), "=r"(a1), "=r"(a2), "=r"(a3) : "l"(f));
        asm volatile("ld.volatile.global.v4.u32 {%0,%1,%2,%3}, [%4];"
                     : "=r"(b0), "=r"(b1), "=r"(b2), "=r"(b3) : "l"(f + 4));
        unsigned m = min(min(min(a0, a1), min(a2, a3)),
                         min(min(b0, b1), min(b2, b3)));
        if (m >= tgt) return;
        __nanosleep(64);
    }
}

// ---------------- prep kernels -------------------------------------------
__global__ void wprep_rec(const float* __restrict__ g_w,
                          const float* __restrict__ a_w) {
    int idx = blockIdx.x * blockDim.x + threadIdx.x;   // NCG*32*C
    int cg = idx >> 15, r = (idx >> 10) & 31, k = idx & 1023;
    int cell = cg * CPC + (r & 15);
    const float* src = (r < 16) ? a_w : g_w;
    split_bf16(src[(size_t)cell * WROW + F + k], g_Awhi[idx], g_Awlo[idx]);
}
__global__ void xprep(const float* __restrict__ x) {
    size_t i = (size_t)blockIdx.x * blockDim.x + threadIdx.x;   // B*T*F
    split_bf16(x[i], g_xhi[i], g_xlo[i]);
}
__global__ void pwprep(const float* __restrict__ u_w,
                       const float* __restrict__ g_w,
                       const float* __restrict__ a_w) {
    int idx = blockIdx.x * blockDim.x + threadIdx.x;   // 3*C*F
    int row = idx >> 8, k = idx & 255;
    float v;
    if (row < C)           v = u_w[(size_t)row * F + k];
    else if (row < 2 * C)  v = g_w[(size_t)(row - C) * WROW + k];
    else                   v = a_w[(size_t)(row - 2 * C) * WROW + k];
    split_bf16(v, g_pwhi[idx], g_pwlo[idx]);
}
__global__ void owprep(const float* __restrict__ o_w) {
    int idx = blockIdx.x * blockDim.x + threadIdx.x;   // KOUT*C
    split_bf16(o_w[idx], g_owhi[idx], g_owlo[idx]);
}
__global__ void hinit(const float* __restrict__ h_in,
                      const float* __restrict__ s,
                      float* __restrict__ out_s) {
    int i = blockIdx.x * blockDim.x + threadIdx.x;
    if (i < BC) {
        int c = i & (C - 1);
        split_bf16(h_in[i] + tanhf(s[c]), g_hshi[i], g_hslo[i]);
    }
    if (i < C) out_s[i] = s[i];
    if (i < 16) ((unsigned*)g_flag)[i] = 0u;
}

// ---------------- generic bf16x3 GEMM bodies -----------------------------
struct GemmFrag {
    uint32_t aoff_h[2], aoff_l[2], boff_h[2], boff_l[2];
    int wm, wn, gid, tig, lane;
};
__device__ __forceinline__ GemmFrag gemm_frag(int tid) {
    GemmFrag f;
    int warp = tid >> 5;
    f.lane = tid & 31;
    f.gid = f.lane >> 2;
    f.tig = f.lane & 3;
    f.wm = warp & 1;
    f.wn = warp >> 1;
    int aRow = ((f.lane >> 3) & 1) * 8 + (f.lane & 7);
    int aCol = ((f.lane >> 4) & 1) * 8;
    int bRow = f.lane & 7;
    int bCol = ((f.lane >> 3) & 1) * 8;
#pragma unroll
    for (int mt = 0; mt < 2; ++mt) {
        f.aoff_h[mt] = (uint32_t)((f.wm * 32 + mt * 16 + aRow) * GP + aCol) * 2;
        f.aoff_l[mt] = (uint32_t)((64 + f.wm * 32 + mt * 16 + aRow) * GP + aCol) * 2;
    }
#pragma unroll
    for (int nt = 0; nt < 2; ++nt) {
        f.boff_h[nt] = (uint32_t)((f.wn * 16 + nt * 8 + bRow) * GP + bCol) * 2;
        f.boff_l[nt] = (uint32_t)((64 + f.wn * 16 + nt * 8 + bRow) * GP + bCol) * 2;
    }
    return f;
}
__device__ __forceinline__ void gemm_load_stage(
    uint32_t sb, int stg,
    const __nv_bfloat16* __restrict__ Ahi, const __nv_bfloat16* __restrict__ Alo,
    int lda,
    const __nv_bfloat16* __restrict__ Bhi, const __nv_bfloat16* __restrict__ Blo,
    int ldb, int k0, int tid) {
    uint32_t base = sb + stg * GSTAGE;
#pragma unroll
    for (int j = 0; j < 4; ++j) {
        int g = tid + j * 256;
        int row = g >> 3, q = g & 7;
        const __nv_bfloat16* src = (row < 64)
            ? Ahi + (size_t)row * lda + k0 + q * 8
            : Alo + (size_t)(row - 64) * lda + k0 + q * 8;
        cpa16(base + (uint32_t)(row * GP + q * 8) * 2, src);
    }
#pragma unroll
    for (int j = 0; j < 4; ++j) {
        int g = tid + j * 256;
        int row = g >> 3, q = g & 7;
        const __nv_bfloat16* src = (row < 64)
            ? Bhi + (size_t)row * ldb + k0 + q * 8
            : Blo + (size_t)(row - 64) * ldb + k0 + q * 8;
        cpa16(base + GSTG + (uint32_t)(row * GP + q * 8) * 2, src);
    }
    CPA_COMMIT();
}
__device__ __forceinline__ void gemm_mma_chunk(uint32_t sb, int stg,
                                               const GemmFrag& f,
                                               float acc[2][2][4]) {
    uint32_t stA = sb + stg * GSTAGE;
    uint32_t stB = stA + GSTG;
#pragma unroll
    for (int ks = 0; ks < 4; ++ks) {
        uint32_t kk = ks * 32;                 // bytes
        uint32_t ah[2][4], al[2][4], bh[2][2], bl[2][2];
#pragma unroll
        for (int mt = 0; mt < 2; ++mt) {
            ldm_x4(ah[mt], stA + f.aoff_h[mt] + kk);
            ldm_x4(al[mt], stA + f.aoff_l[mt] + kk);
        }
#pragma unroll
        for (int nt = 0; nt < 2; ++nt) {
            ldm_x2(bh[nt], stB + f.boff_h[nt] + kk);
            ldm_x2(bl[nt], stB + f.boff_l[nt] + kk);
        }
#pragma unroll
        for (int mt = 0; mt < 2; ++mt)
#pragma unroll
            for (int nt = 0; nt < 2; ++nt) {
                mma16816(acc[mt][nt], ah[mt], bh[nt]);
                mma16816(acc[mt][nt], ah[mt], bl[nt]);
                mma16816(acc[mt][nt], al[mt], bh[nt]);
            }
    }
}
__device__ __forceinline__ void gemm_transpose(char* smem, const GemmFrag& f,
                                               float acc[2][2][4]) {
    __syncthreads();
    float* tr = (float*)smem;                  // [n 64][m 64+4]
#pragma unroll
    for (int mt = 0; mt < 2; ++mt)
#pragma unroll
        for (int nt = 0; nt < 2; ++nt)
#pragma unroll
            for (int j = 0; j < 4; ++j) {
                int n = f.wn * 16 + nt * 8 + 2 * f.tig + (j & 1);
                int m = f.wm * 32 + mt * 16 + f.gid + (j >> 1) * 8;
                tr[n * 68 + m] = acc[mt][nt][j];
            }
    __syncthreads();
}

// ---------------- pre GEMM: [U|GX|AX] = x @ W^T + bias -------------------
__global__ void __launch_bounds__(256) pre_gemm_bf16(
    const float* __restrict__ u_b, const float* __restrict__ g_b) {
    extern __shared__ char smem[];
    const uint32_t sb = smem_u32(smem);
    const int tid = threadIdx.x;
    const int n0 = blockIdx.x * 64;            // x rows
    const int m0 = blockIdx.y * 64;            // weight rows (0..3071)
    const GemmFrag f = gemm_frag(tid);

    const __nv_bfloat16* Ahi = g_pwhi + (size_t)m0 * F;
    const __nv_bfloat16* Alo = g_pwlo + (size_t)m0 * F;
    const __nv_bfloat16* Bhi = g_xhi + (size_t)n0 * F;
    const __nv_bfloat16* Blo = g_xlo + (size_t)n0 * F;

    float acc[2][2][4] = {};
    const int NC = F / 64;                     // 4 chunks
    gemm_load_stage(sb, 0, Ahi, Alo, F, Bhi, Blo, F, 0, tid);
    gemm_load_stage(sb, 1, Ahi, Alo, F, Bhi, Blo, F, 64, tid);
    gemm_load_stage(sb, 2, Ahi, Alo, F, Bhi, Blo, F, 128, tid);
#pragma unroll 1
    for (int c = 0; c < NC; ++c) {
        int pend = NC - 1 - c;
        if (pend >= 2) CPA_WAIT(2); else if (pend == 1) CPA_WAIT(1); else CPA_WAIT(0);
        __syncthreads();
        gemm_mma_chunk(sb, c % 3, f, acc);
        if (c + 3 < NC) {
            __syncthreads();
            gemm_load_stage(sb, c % 3, Ahi, Alo, F, Bhi, Blo, F, (c + 3) * 64, tid);
        }
    }
    gemm_transpose(smem, f, acc);

    const int which = m0 >> 10;
    const int cbase = m0 & 1023;
    float* dst = (which == 0) ? g_U : (which == 1) ? g_GX : g_AX;
    const float* bias = (which == 0) ? u_b : (which == 1) ? g_b : nullptr;
    const float* tr = (const float*)smem;
    const int n = tid >> 2;
    const int n_g = n0 + n;
    const int b = n_g >> 9, t = n_g & 511;     // n_g = b*T + t
    float* drow = dst + (size_t)t * BC + (size_t)b * C + cbase;
#pragma unroll
    for (int q = 0; q < 4; ++q) {
        int m = ((tid & 3) * 4 + q) * 4;
        float4 v = *(const float4*)&tr[n * 68 + m];
        if (bias) {
            float4 bv = *(const float4*)&bias[cbase + m];
            v.x += bv.x; v.y += bv.y; v.z += bv.z; v.w += bv.w;
        }
        *(float4*)&drow[m] = v;
    }
}

// ---------------- out GEMM: outs[b][t][:] = h_t @ o_w^T + o_b ------------
__global__ void __launch_bounds__(256) out_gemm_bf16(
    const float* __restrict__ o_b, float* __restrict__ outp) {
    extern __shared__ char smem[];
    const uint32_t sb = smem_u32(smem);
    const int tid = threadIdx.x;
    const int tslot = blockIdx.x;              // t: h_t stored at slot t+1
    const int m0 = blockIdx.y * 64;            // out-class rows
    const GemmFrag f = gemm_frag(tid);

    const __nv_bfloat16* Ahi = g_owhi + (size_t)m0 * C;
    const __nv_bfloat16* Alo = g_owlo + (size_t)m0 * C;
    const __nv_bfloat16* Bhi = g_hshi + (size_t)(tslot + 1) * BC;
    const __nv_bfloat16* Blo = g_hslo + (size_t)(tslot + 1) * BC;

    float acc[2][2][4] = {};
    const int NC = C / 64;                     // 16 chunks
    gemm_load_stage(sb, 0, Ahi, Alo, C, Bhi, Blo, C, 0, tid);
    gemm_load_stage(sb, 1, Ahi, Alo, C, Bhi, Blo, C, 64, tid);
    gemm_load_stage(sb, 2, Ahi, Alo, C, Bhi, Blo, C, 128, tid);
#pragma unroll 1
    for (int c = 0; c < NC; ++c) {
        int pend = NC - 1 - c;
        if (pend >= 2) CPA_WAIT(2); else if (pend == 1) CPA_WAIT(1); else CPA_WAIT(0);
        __syncthreads();
        gemm_mma_chunk(sb, c % 3, f, acc);
        if (c + 3 < NC) {
            __syncthreads();
            gemm_load_stage(sb, c % 3, Ahi, Alo, C, Bhi, Blo, C, (c + 3) * 64, tid);
        }
    }
    gemm_transpose(smem, f, acc);

    const float* tr = (const float*)smem;
    const int b = tid >> 2;                    // n index = batch
    float* drow = outp + (size_t)b * T * KOUT + (size_t)tslot * KOUT + m0;
#pragma unroll
    for (int q = 0; q < 4; ++q) {
        int m = ((tid & 3) * 4 + q) * 4;
        float4 v = *(const float4*)&tr[b * 68 + m];
        float4 bv = *(const float4*)&o_b[m0 + m];
        v.x += bv.x; v.y += bv.y; v.z += bv.z; v.w += bv.w;
        *(float4*)&drow[m] = v;
    }
}

// ---------------- recurrent chunk loader (512 threads, 1 pass) -----------
__device__ __forceinline__ void rec_load_chunk(
    int p, int s, uint32_t sb, const __nv_bfloat16* __restrict__ hhi,
    const __nv_bfloat16* __restrict__ hlo, int bbase, int tid) {
    int row = tid >> 4, q = tid & 15;          // 32 rows x 16 pieces
    uint32_t d0 = sb + SB_OFF(s) + (uint32_t)(row * BPITCH) * 2 + q * 16;
    const __nv_bfloat16* s0 = hhi + (size_t)(bbase + row) * C + p * 128 + q * 8;
    const __nv_bfloat16* s1 = hlo + (size_t)(bbase + row) * C + p * 128 + q * 8;
    cpa16(d0, s0);
    cpa16(d0 + B_HALF, s1);
    CPA_COMMIT();
}

// ---------------- persistent recurrent kernel (16 warps, k-quarters) -----
__global__ void __launch_bounds__(RTHR, 1) rec_kernel(
    const float* __restrict__ n_in, const float* __restrict__ d_in,
    const float* __restrict__ amax_in,
    float* __restrict__ out_n, float* __restrict__ out_d,
    float* __restrict__ out_h, float* __restrict__ out_amax) {
    extern __shared__ char smem[];
    const uint32_t sb = smem_u32(smem);
    float* red = (float*)(smem + RED_OFF);     // [3 kq][8 q][128 thr]

    const int tid   = threadIdx.x;
    const int warp  = tid >> 5;
    const int lane  = tid & 31;
    const int gid   = lane >> 2;
    const int tig   = lane & 3;
    const int wn    = warp & 3;                // n-tile: batches wn*8..+7
    const int kq    = warp >> 2;               // k-quarter within 128-chunk
    const int cg    = blockIdx.x >> 1;
    const int bh    = blockIdx.x & 1;
    const int bbase = bh * NB;
    const int rot   = cg >> 3;                 // starting chunk = own group

    // ---- prologue: resident weights into smem ----
    for (int i = tid; i < 64 * 128; i += RTHR) {
        int row = i >> 7, q = i & 127;
        const __nv_bfloat16* src = (row < 32)
            ? g_Awhi + ((size_t)cg * 32 + row) * C + q * 8
            : g_Awlo + ((size_t)cg * 32 + row - 32) * C + q * 8;
        cpa16(sb + (uint32_t)(row * APITCH + q * 8) * 2, src);
    }
    CPA_COMMIT();

    const int aRow = ((lane >> 3) & 1) * 8 + (lane & 7);
    const int aCol = ((lane >> 4) & 1) * 8;
    const uint32_t aHi0 = sb + (uint32_t)((aRow)      * APITCH + aCol) * 2;
    const uint32_t aHi1 = sb + (uint32_t)((16 + aRow) * APITCH + aCol) * 2;
    const uint32_t aLo0 = sb + (uint32_t)((32 + aRow) * APITCH + aCol) * 2;
    const uint32_t aLo1 = sb + (uint32_t)((48 + aRow) * APITCH + aCol) * 2;
    // fused B x4: lanes 0-15 -> Bhi tiles, lanes 16-31 -> Blo tiles
    const uint32_t bOffF = (uint32_t)(lane >> 4) * B_HALF
        + (uint32_t)((wn * 8 + (lane & 7)) * BPITCH + ((lane >> 3) & 1) * 8) * 2;

    float sn[4], sd[4], sa[4];
    if (kq == 0) {
#pragma unroll
        for (int p = 0; p < 4; ++p) {
            int b  = bbase + wn * 8 + 2 * tig + (p & 1);
            int cc = cg * CPC + gid + (p >> 1) * 8;
            sn[p] = n_in[b * C + cc];
            sd[p] = d_in[b * C + cc];
            sa[p] = amax_in[b * C + cc];
        }
    }

    for (int t = 0; t < T; ++t) {
        const __nv_bfloat16* hhi = g_hshi + (size_t)t * BC;
        const __nv_bfloat16* hlo = g_hslo + (size_t)t * BC;
        const unsigned tgt = 8u * (unsigned)t;

        // early epilogue-operand prefetch (DRAM, hidden under MMA loop)
        const size_t tb = (size_t)t * BC;
        float ax[4], gx[4], ux[4];
        if (kq == 0) {
#pragma unroll
            for (int p = 0; p < 4; ++p) {
                int b  = bbase + wn * 8 + 2 * tig + (p & 1);
                int cc = cg * CPC + gid + (p >> 1) * 8;
                size_t idx = tb + (size_t)b * C + cc;
                ax[p] = __ldg(&g_AX[idx]);
                gx[p] = __ldg(&g_GX[idx]);
                ux[p] = __ldg(&g_U[idx]);
            }
        }

        // ---- single wait point: all 8 producer groups of step t-1 done ----
        if (tid == 0) {
            flag_wait8(&g_flag[bh][0], tgt);
            __threadfence();
        }
        __syncthreads();
        rec_load_chunk(rot, 0, sb, hhi, hlo, bbase, tid);
        rec_load_chunk((rot + 1) & 7, 1, sb, hhi, hlo, bbase, tid);

        float acc[8];
#pragma unroll
        for (int q = 0; q < 8; ++q) acc[q] = 0.f;

#pragma unroll 1
        for (int i = 0; i < 8; ++i) {
            const int p = (rot + i) & 7;
            if (i < 7) CPA_WAIT(1); else CPA_WAIT(0);
            __syncthreads();                  // stage (i+2)%3 free (used at i-1)
            if (i < 6)
                rec_load_chunk((rot + i + 2) & 7, (i + 2) % NSTG, sb, hhi, hlo,
                               bbase, tid);
            const uint32_t stg = sb + SB_OFF(i % NSTG);
#pragma unroll
            for (int ks = 0; ks < 2; ++ks) {
                const int ka = p * 128 + kq * 32 + ks * 16;
                const int kb = kq * 32 + ks * 16;
                uint32_t ah0[4], ah1[4], al0[4], al1[4], bf[4];
                ldm_x4(ah0, aHi0 + ka * 2);
                ldm_x4(ah1, aHi1 + ka * 2);
                ldm_x4(bf,  stg + bOffF + kb * 2);   // {bh0,bh1,bl0,bl1}
                ldm_x4(al0, aLo0 + ka * 2);
                ldm_x4(al1, aLo1 + ka * 2);
                mma16816(acc + 0, ah0, bf);
                mma16816(acc + 4, ah1, bf);
                mma16816(acc + 0, ah0, bf + 2);
                mma16816(acc + 4, ah1, bf + 2);
                mma16816(acc + 0, al0, bf);
                mma16816(acc + 4, al1, bf);
            }
        }

        // ---- 4-way reduce + online-softmax epilogue ----
        if (kq != 0) {
            float* dst = red + (kq - 1) * 1024 + wn * 32 + lane;
#pragma unroll
            for (int q = 0; q < 8; ++q) dst[q * 128] = acc[q];
        }
        __syncthreads();
        if (kq == 0) {
            const float* sp = red + wn * 32 + lane;
            __nv_bfloat16* whi = g_hshi + (size_t)(t + 1) * BC;
            __nv_bfloat16* wlo = g_hslo + (size_t)(t + 1) * BC;
#pragma unroll
            for (int q = 0; q < 8; ++q)
                acc[q] += sp[q * 128] + sp[1024 + q * 128] + sp[2048 + q * 128];
#pragma unroll
            for (int p = 0; p < 4; ++p) {
                int b  = bbase + wn * 8 + 2 * tig + (p & 1);
                int cc = cg * CPC + gid + (p >> 1) * 8;
                float at = acc[p] + ax[p];
                float gt = acc[4 + p] + gx[p];
                float z  = ux[p] * tanhf(gt);
                float an = fmaxf(sa[p], at);
                float ed = expf(sa[p] - an);
                float es = expf(at - an);
                sn[p] = sn[p] * ed + z * es;
                sd[p] = sd[p] * ed + es;
                float h = tanhf(sn[p] / sd[p]);
                sa[p] = an;
                __nv_bfloat16 hi, lo;
                split_bf16(h, hi, lo);
                whi[b * C + cc] = hi;
                wlo[b * C + cc] = lo;
            }
            __threadfence();
        }
        __syncthreads();
        if (tid == 0) atomicAdd(&g_flag[bh][rot], 1u);
    }

    if (kq == 0) {
#pragma unroll
        for (int p = 0; p < 4; ++p) {
            int b  = bbase + wn * 8 + 2 * tig + (p & 1);
            int cc = cg * CPC + gid + (p >> 1) * 8;
            out_n[b * C + cc]    = sn[p];
            out_d[b * C + cc]    = sd[p];
            out_h[b * C + cc]    = tanhf(sn[p] / sd[p]);
            out_amax[b * C + cc] = sa[p];
        }
    }
}

// ---------------- launch ---------------------------------------------------
extern "C" void kernel_launch(void* const* d_in, const int* in_sizes, int n_in,
                              void* d_out, int out_size) {
    (void)in_sizes; (void)n_in; (void)out_size;
    const float* x      = (const float*)d_in[0];
    const float* s      = (const float*)d_in[1];
    const float* n0     = (const float*)d_in[2];
    const float* d0     = (const float*)d_in[3];
    const float* h0     = (const float*)d_in[4];
    const float* amax0  = (const float*)d_in[5];
    const float* u_w    = (const float*)d_in[6];
    const float* u_b    = (const float*)d_in[7];
    const float* g_w    = (const float*)d_in[8];
    const float* g_b    = (const float*)d_in[9];
    const float* a_w    = (const float*)d_in[10];
    const float* o_w    = (const float*)d_in[11];
    const float* o_b    = (const float*)d_in[12];

    float* out        = (float*)d_out;
    float* out_outs   = out;
    float* out_s      = out + (size_t)B * T * KOUT;
    float* out_n      = out_s + C;
    float* out_d      = out_n + (size_t)B * C;
    float* out_h      = out_d + (size_t)B * C;
    float* out_amax   = out_h + (size_t)B * C;

    cudaFuncSetAttribute(rec_kernel, cudaFuncAttributeMaxDynamicSharedMemorySize, RSMEM);
    cudaFuncSetAttribute(pre_gemm_bf16, cudaFuncAttributeMaxDynamicSharedMemorySize, GSMEM);
    cudaFuncSetAttribute(out_gemm_bf16, cudaFuncAttributeMaxDynamicSharedMemorySize, GSMEM);

    wprep_rec<<<NCG * 32 * C / 256, 256>>>(g_w, a_w);
    xprep<<<(B * T * F) / 256, 256>>>(x);
    pwprep<<<(3 * C * F) / 256, 256>>>(u_w, g_w, a_w);
    owprep<<<(KOUT * C) / 256, 256>>>(o_w);
    hinit<<<(BC + 255) / 256, 256>>>(h0, s, out_s);
    pre_gemm_bf16<<<dim3(512, 48), 256, GSMEM>>>(u_b, g_b);
    rec_kernel<<<RCTA, RTHR, RSMEM>>>(n0, d0, amax0,
                                      out_n, out_d, out_h, out_amax);
    out_gemm_bf16<<<dim3(512, 4), 256, GSMEM>>>(o_b, out_outs);
}

// round 10
// speedup vs baseline: 1.4922x; 1.0463x over previous
#include <cuda_runtime.h>
#include <cuda_bf16.h>
#include <cstdint>

#define B 64
#define T 512
#define F 256
#define C 1024
#define KOUT 256
#define BC (B * C)
#define WROW (F + C)          // 1280 floats per g_w/a_w row

// ---------------- recurrent kernel config --------------------------------
#define RCTA 128              // (cg 0..63) x (batch-half 0..1)
#define NCG  64               // cell groups
#define RTHR 512              // 16 warps: kq = warp>>2, wn = warp&3
#define CPC  16               // cells per CTA  (A tile M = 32 = 16 a + 16 g)
#define NB   32               // batches per CTA
#define CH   256              // k per chunk
#define NCH  4                // chunks per step
#define APITCH 1032           // smem A pitch (bf16)
#define BP2 264               // smem B pitch (bf16), row 528 B
#define BROWB (BP2 * 2)       // 528
#define BHALF2 16896          // 32 rows * 528
#define BSTG2 (2 * BHALF2)    // 33792 (hi + lo)
#define A_BYTES (64 * APITCH * 2)              // 132096
#define SB2(s) (A_BYTES + (s) * BSTG2)
#define RED_OFF (A_BYTES + 2 * BSTG2)          // 199680
#define RSMEM (RED_OFF + 16384)                // 216064

// ---------------- bf16 GEMM (pre/out) config -----------------------------
#define GP 72                                   // smem pitch (bf16)
#define GSTG (128 * GP * 2)                     // 18432 B per operand stage
#define GSTAGE (2 * GSTG)                       // 36864
#define GSMEM (3 * GSTAGE)                      // 110592

// ---------------- device scratch -----------------------------------------
__device__ __align__(16) float g_U [(size_t)T * BC];
__device__ __align__(16) float g_GX[(size_t)T * BC];
__device__ __align__(16) float g_AX[(size_t)T * BC];
__device__ __align__(16) __nv_bfloat16 g_hshi[(size_t)(T + 1) * BC]; // h slots
__device__ __align__(16) __nv_bfloat16 g_hslo[(size_t)(T + 1) * BC];
__device__ __align__(16) __nv_bfloat16 g_Awhi[NCG * 32 * C];  // rec weights
__device__ __align__(16) __nv_bfloat16 g_Awlo[NCG * 32 * C];
__device__ __align__(16) __nv_bfloat16 g_xhi[(size_t)B * T * F];
__device__ __align__(16) __nv_bfloat16 g_xlo[(size_t)B * T * F];
__device__ __align__(16) __nv_bfloat16 g_pwhi[3 * C * F];     // u/gF/aF rows
__device__ __align__(16) __nv_bfloat16 g_pwlo[3 * C * F];
__device__ __align__(16) __nv_bfloat16 g_owhi[KOUT * C];
__device__ __align__(16) __nv_bfloat16 g_owlo[KOUT * C];
__device__ __align__(32) unsigned g_flag[2][4];

// ---------------- helpers -------------------------------------------------
__device__ __forceinline__ uint32_t smem_u32(const void* p) {
    uint32_t a;
    asm("{ .reg .u64 t; cvta.to.shared.u64 t, %1; cvt.u32.u64 %0, t; }"
        : "=r"(a) : "l"(p));
    return a;
}
__device__ __forceinline__ void cpa16(uint32_t dst, const void* src) {
    asm volatile("cp.async.cg.shared.global [%0], [%1], 16;"
                 :: "r"(dst), "l"(src) : "memory");
}
#define CPA_COMMIT() asm volatile("cp.async.commit_group;" ::: "memory")
#define CPA_WAIT(n)  asm volatile("cp.async.wait_group %0;" :: "n"(n) : "memory")

__device__ __forceinline__ void mma16816(float* d, const uint32_t* a,
                                         const uint32_t* b) {
    asm volatile(
        "mma.sync.aligned.m16n8k16.row.col.f32.bf16.bf16.f32 "
        "{%0,%1,%2,%3},{%4,%5,%6,%7},{%8,%9},{%0,%1,%2,%3};"
        : "+f"(d[0]), "+f"(d[1]), "+f"(d[2]), "+f"(d[3])
        : "r"(a[0]), "r"(a[1]), "r"(a[2]), "r"(a[3]), "r"(b[0]), "r"(b[1]));
}
__device__ __forceinline__ void ldm_x4(uint32_t* r, uint32_t a) {
    asm volatile("ldmatrix.sync.aligned.m8n8.x4.shared.b16 {%0,%1,%2,%3}, [%4];"
                 : "=r"(r[0]), "=r"(r[1]), "=r"(r[2]), "=r"(r[3]) : "r"(a));
}
__device__ __forceinline__ void ldm_x2(uint32_t* r, uint32_t a) {
    asm volatile("ldmatrix.sync.aligned.m8n8.x2.shared.b16 {%0,%1}, [%2];"
                 : "=r"(r[0]), "=r"(r[1]) : "r"(a));
}
__device__ __forceinline__ void split_bf16(float v, __nv_bfloat16& hi,
                                           __nv_bfloat16& lo) {
    hi = __float2bfloat16_rn(v);
    lo = __float2bfloat16_rn(v - __bfloat162float(hi));
}
// poll all 4 producer flags with one volatile v4 load; pure spin (1 thr/CTA)
__device__ __forceinline__ void flag_wait4(const unsigned* f, unsigned tgt) {
    for (;;) {
        unsigned a0, a1, a2, a3;
        asm volatile("ld.volatile.global.v4.u32 {%0,%1,%2,%3}, [%4];"
                     : "=r"(a0), "=r"(a1), "=r"(a2), "=r"(a3) : "l"(f));
        if (min(min(a0, a1), min(a2, a3)) >= tgt) return;
    }
}

// ---------------- prep kernels -------------------------------------------
__global__ void wprep_rec(const float* __restrict__ g_w,
                          const float* __restrict__ a_w) {
    int idx = blockIdx.x * blockDim.x + threadIdx.x;   // NCG*32*C
    int cg = idx >> 15, r = (idx >> 10) & 31, k = idx & 1023;
    int cell = cg * CPC + (r & 15);
    const float* src = (r < 16) ? a_w : g_w;
    split_bf16(src[(size_t)cell * WROW + F + k], g_Awhi[idx], g_Awlo[idx]);
}
__global__ void xprep(const float* __restrict__ x) {
    size_t i = (size_t)blockIdx.x * blockDim.x + threadIdx.x;   // B*T*F
    split_bf16(x[i], g_xhi[i], g_xlo[i]);
}
__global__ void pwprep(const float* __restrict__ u_w,
                       const float* __restrict__ g_w,
                       const float* __restrict__ a_w) {
    int idx = blockIdx.x * blockDim.x + threadIdx.x;   // 3*C*F
    int row = idx >> 8, k = idx & 255;
    float v;
    if (row < C)           v = u_w[(size_t)row * F + k];
    else if (row < 2 * C)  v = g_w[(size_t)(row - C) * WROW + k];
    else                   v = a_w[(size_t)(row - 2 * C) * WROW + k];
    split_bf16(v, g_pwhi[idx], g_pwlo[idx]);
}
__global__ void owprep(const float* __restrict__ o_w) {
    int idx = blockIdx.x * blockDim.x + threadIdx.x;   // KOUT*C
    split_bf16(o_w[idx], g_owhi[idx], g_owlo[idx]);
}
__global__ void hinit(const float* __restrict__ h_in,
                      const float* __restrict__ s,
                      float* __restrict__ out_s) {
    int i = blockIdx.x * blockDim.x + threadIdx.x;
    if (i < BC) {
        int c = i & (C - 1);
        split_bf16(h_in[i] + tanhf(s[c]), g_hshi[i], g_hslo[i]);
    }
    if (i < C) out_s[i] = s[i];
    if (i < 8) ((unsigned*)g_flag)[i] = 0u;
}

// ---------------- generic bf16x3 GEMM bodies -----------------------------
struct GemmFrag {
    uint32_t aoff_h[2], aoff_l[2], boff_h[2], boff_l[2];
    int wm, wn, gid, tig, lane;
};
__device__ __forceinline__ GemmFrag gemm_frag(int tid) {
    GemmFrag f;
    int warp = tid >> 5;
    f.lane = tid & 31;
    f.gid = f.lane >> 2;
    f.tig = f.lane & 3;
    f.wm = warp & 1;
    f.wn = warp >> 1;
    int aRow = ((f.lane >> 3) & 1) * 8 + (f.lane & 7);
    int aCol = ((f.lane >> 4) & 1) * 8;
    int bRow = f.lane & 7;
    int bCol = ((f.lane >> 3) & 1) * 8;
#pragma unroll
    for (int mt = 0; mt < 2; ++mt) {
        f.aoff_h[mt] = (uint32_t)((f.wm * 32 + mt * 16 + aRow) * GP + aCol) * 2;
        f.aoff_l[mt] = (uint32_t)((64 + f.wm * 32 + mt * 16 + aRow) * GP + aCol) * 2;
    }
#pragma unroll
    for (int nt = 0; nt < 2; ++nt) {
        f.boff_h[nt] = (uint32_t)((f.wn * 16 + nt * 8 + bRow) * GP + bCol) * 2;
        f.boff_l[nt] = (uint32_t)((64 + f.wn * 16 + nt * 8 + bRow) * GP + bCol) * 2;
    }
    return f;
}
__device__ __forceinline__ void gemm_load_stage(
    uint32_t sb, int stg,
    const __nv_bfloat16* __restrict__ Ahi, const __nv_bfloat16* __restrict__ Alo,
    int lda,
    const __nv_bfloat16* __restrict__ Bhi, const __nv_bfloat16* __restrict__ Blo,
    int ldb, int k0, int tid) {
    uint32_t base = sb + stg * GSTAGE;
#pragma unroll
    for (int j = 0; j < 4; ++j) {
        int g = tid + j * 256;
        int row = g >> 3, q = g & 7;
        const __nv_bfloat16* src = (row < 64)
            ? Ahi + (size_t)row * lda + k0 + q * 8
            : Alo + (size_t)(row - 64) * lda + k0 + q * 8;
        cpa16(base + (uint32_t)(row * GP + q * 8) * 2, src);
    }
#pragma unroll
    for (int j = 0; j < 4; ++j) {
        int g = tid + j * 256;
        int row = g >> 3, q = g & 7;
        const __nv_bfloat16* src = (row < 64)
            ? Bhi + (size_t)row * ldb + k0 + q * 8
            : Blo + (size_t)(row - 64) * ldb + k0 + q * 8;
        cpa16(base + GSTG + (uint32_t)(row * GP + q * 8) * 2, src);
    }
    CPA_COMMIT();
}
__device__ __forceinline__ void gemm_mma_chunk(uint32_t sb, int stg,
                                               const GemmFrag& f,
                                               float acc[2][2][4]) {
    uint32_t stA = sb + stg * GSTAGE;
    uint32_t stB = stA + GSTG;
#pragma unroll
    for (int ks = 0; ks < 4; ++ks) {
        uint32_t kk = ks * 32;                 // bytes
        uint32_t ah[2][4], al[2][4], bh[2][2], bl[2][2];
#pragma unroll
        for (int mt = 0; mt < 2; ++mt) {
            ldm_x4(ah[mt], stA + f.aoff_h[mt] + kk);
            ldm_x4(al[mt], stA + f.aoff_l[mt] + kk);
        }
#pragma unroll
        for (int nt = 0; nt < 2; ++nt) {
            ldm_x2(bh[nt], stB + f.boff_h[nt] + kk);
            ldm_x2(bl[nt], stB + f.boff_l[nt] + kk);
        }
#pragma unroll
        for (int mt = 0; mt < 2; ++mt)
#pragma unroll
            for (int nt = 0; nt < 2; ++nt) {
                mma16816(acc[mt][nt], ah[mt], bh[nt]);
                mma16816(acc[mt][nt], ah[mt], bl[nt]);
                mma16816(acc[mt][nt], al[mt], bh[nt]);
            }
    }
}
__device__ __forceinline__ void gemm_transpose(char* smem, const GemmFrag& f,
                                               float acc[2][2][4]) {
    __syncthreads();
    float* tr = (float*)smem;                  // [n 64][m 64+4]
#pragma unroll
    for (int mt = 0; mt < 2; ++mt)
#pragma unroll
        for (int nt = 0; nt < 2; ++nt)
#pragma unroll
            for (int j = 0; j < 4; ++j) {
                int n = f.wn * 16 + nt * 8 + 2 * f.tig + (j & 1);
                int m = f.wm * 32 + mt * 16 + f.gid + (j >> 1) * 8;
                tr[n * 68 + m] = acc[mt][nt][j];
            }
    __syncthreads();
}

// ---------------- pre GEMM: [U|GX|AX] = x @ W^T + bias -------------------
__global__ void __launch_bounds__(256) pre_gemm_bf16(
    const float* __restrict__ u_b, const float* __restrict__ g_b) {
    extern __shared__ char smem[];
    const uint32_t sb = smem_u32(smem);
    const int tid = threadIdx.x;
    const int n0 = blockIdx.x * 64;            // x rows
    const int m0 = blockIdx.y * 64;            // weight rows (0..3071)
    const GemmFrag f = gemm_frag(tid);

    const __nv_bfloat16* Ahi = g_pwhi + (size_t)m0 * F;
    const __nv_bfloat16* Alo = g_pwlo + (size_t)m0 * F;
    const __nv_bfloat16* Bhi = g_xhi + (size_t)n0 * F;
    const __nv_bfloat16* Blo = g_xlo + (size_t)n0 * F;

    float acc[2][2][4] = {};
    const int NC = F / 64;                     // 4 chunks
    gemm_load_stage(sb, 0, Ahi, Alo, F, Bhi, Blo, F, 0, tid);
    gemm_load_stage(sb, 1, Ahi, Alo, F, Bhi, Blo, F, 64, tid);
    gemm_load_stage(sb, 2, Ahi, Alo, F, Bhi, Blo, F, 128, tid);
#pragma unroll 1
    for (int c = 0; c < NC; ++c) {
        int pend = NC - 1 - c;
        if (pend >= 2) CPA_WAIT(2); else if (pend == 1) CPA_WAIT(1); else CPA_WAIT(0);
        __syncthreads();
        gemm_mma_chunk(sb, c % 3, f, acc);
        if (c + 3 < NC) {
            __syncthreads();
            gemm_load_stage(sb, c % 3, Ahi, Alo, F, Bhi, Blo, F, (c + 3) * 64, tid);
        }
    }
    gemm_transpose(smem, f, acc);

    const int which = m0 >> 10;
    const int cbase = m0 & 1023;
    float* dst = (which == 0) ? g_U : (which == 1) ? g_GX : g_AX;
    const float* bias = (which == 0) ? u_b : (which == 1) ? g_b : nullptr;
    const float* tr = (const float*)smem;
    const int n = tid >> 2;
    const int n_g = n0 + n;
    const int b = n_g >> 9, t = n_g & 511;     // n_g = b*T + t
    float* drow = dst + (size_t)t * BC + (size_t)b * C + cbase;
#pragma unroll
    for (int q = 0; q < 4; ++q) {
        int m = ((tid & 3) * 4 + q) * 4;
        float4 v = *(const float4*)&tr[n * 68 + m];
        if (bias) {
            float4 bv = *(const float4*)&bias[cbase + m];
            v.x += bv.x; v.y += bv.y; v.z += bv.z; v.w += bv.w;
        }
        *(float4*)&drow[m] = v;
    }
}

// ---------------- out GEMM: outs[b][t][:] = h_t @ o_w^T + o_b ------------
__global__ void __launch_bounds__(256) out_gemm_bf16(
    const float* __restrict__ o_b, float* __restrict__ outp) {
    extern __shared__ char smem[];
    const uint32_t sb = smem_u32(smem);
    const int tid = threadIdx.x;
    const int tslot = blockIdx.x;              // t: h_t stored at slot t+1
    const int m0 = blockIdx.y * 64;            // out-class rows
    const GemmFrag f = gemm_frag(tid);

    const __nv_bfloat16* Ahi = g_owhi + (size_t)m0 * C;
    const __nv_bfloat16* Alo = g_owlo + (size_t)m0 * C;
    const __nv_bfloat16* Bhi = g_hshi + (size_t)(tslot + 1) * BC;
    const __nv_bfloat16* Blo = g_hslo + (size_t)(tslot + 1) * BC;

    float acc[2][2][4] = {};
    const int NC = C / 64;                     // 16 chunks
    gemm_load_stage(sb, 0, Ahi, Alo, C, Bhi, Blo, C, 0, tid);
    gemm_load_stage(sb, 1, Ahi, Alo, C, Bhi, Blo, C, 64, tid);
    gemm_load_stage(sb, 2, Ahi, Alo, C, Bhi, Blo, C, 128, tid);
#pragma unroll 1
    for (int c = 0; c < NC; ++c) {
        int pend = NC - 1 - c;
        if (pend >= 2) CPA_WAIT(2); else if (pend == 1) CPA_WAIT(1); else CPA_WAIT(0);
        __syncthreads();
        gemm_mma_chunk(sb, c % 3, f, acc);
        if (c + 3 < NC) {
            __syncthreads();
            gemm_load_stage(sb, c % 3, Ahi, Alo, C, Bhi, Blo, C, (c + 3) * 64, tid);
        }
    }
    gemm_transpose(smem, f, acc);

    const float* tr = (const float*)smem;
    const int b = tid >> 2;                    // n index = batch
    float* drow = outp + (size_t)b * T * KOUT + (size_t)tslot * KOUT + m0;
#pragma unroll
    for (int q = 0; q < 4; ++q) {
        int m = ((tid & 3) * 4 + q) * 4;
        float4 v = *(const float4*)&tr[b * 68 + m];
        float4 bv = *(const float4*)&o_b[m0 + m];
        v.x += bv.x; v.y += bv.y; v.z += bv.z; v.w += bv.w;
        *(float4*)&drow[m] = v;
    }
}

// ---------------- recurrent chunk loader (256-wide, 512 threads) ---------
__device__ __forceinline__ void rec_load_chunk(
    int p, int s, uint32_t sb, const __nv_bfloat16* __restrict__ hhi,
    const __nv_bfloat16* __restrict__ hlo, int bbase, int tid) {
#pragma unroll
    for (int j = 0; j < 4; ++j) {
        int i = tid + j * RTHR;                // 0..2047
        int half = i >> 10, r = (i >> 5) & 31, q2 = i & 31;
        uint32_t d = sb + SB2(s) + half * BHALF2
                   + (uint32_t)(r * BROWB) + q2 * 16;
        const __nv_bfloat16* src = (half ? hlo : hhi)
            + (size_t)(bbase + r) * C + p * CH + q2 * 8;
        cpa16(d, src);
    }
    CPA_COMMIT();
}

// ---------------- persistent recurrent kernel (4x256 chunks) -------------
__global__ void __launch_bounds__(RTHR, 1) rec_kernel(
    const float* __restrict__ n_in, const float* __restrict__ d_in,
    const float* __restrict__ amax_in,
    float* __restrict__ out_n, float* __restrict__ out_d,
    float* __restrict__ out_h, float* __restrict__ out_amax) {
    extern __shared__ char smem[];
    const uint32_t sb = smem_u32(smem);
    float* red = (float*)(smem + RED_OFF);     // [4 kq][8 q][128]

    const int tid   = threadIdx.x;
    const int warp  = tid >> 5;
    const int lane  = tid & 31;
    const int wn    = warp & 3;                // n-tile: batches wn*8..+7
    const int kq    = warp >> 2;               // k-quarter (64) within chunk
    const int cg    = blockIdx.x >> 1;
    const int bh    = blockIdx.x & 1;
    const int bbase = bh * NB;
    const int rot   = cg >> 4;                 // starting chunk (0..3)

    // ---- prologue: resident weights into smem ----
    for (int i = tid; i < 64 * 128; i += RTHR) {
        int row = i >> 7, q = i & 127;
        const __nv_bfloat16* src = (row < 32)
            ? g_Awhi + ((size_t)cg * 32 + row) * C + q * 8
            : g_Awlo + ((size_t)cg * 32 + row - 32) * C + q * 8;
        cpa16(sb + (uint32_t)(row * APITCH + q * 8) * 2, src);
    }
    CPA_COMMIT();

    const int aRow = ((lane >> 3) & 1) * 8 + (lane & 7);
    const int aCol = ((lane >> 4) & 1) * 8;
    const uint32_t aHi0 = sb + (uint32_t)((aRow)      * APITCH + aCol) * 2;
    const uint32_t aHi1 = sb + (uint32_t)((16 + aRow) * APITCH + aCol) * 2;
    const uint32_t aLo0 = sb + (uint32_t)((32 + aRow) * APITCH + aCol) * 2;
    const uint32_t aLo1 = sb + (uint32_t)((48 + aRow) * APITCH + aCol) * 2;
    // fused B x4: lanes 0-15 -> Bhi tile, lanes 16-31 -> Blo tile
    const uint32_t bOffF = (uint32_t)(lane >> 4) * BHALF2
        + (uint32_t)((wn * 8 + (lane & 7)) * BP2 + ((lane >> 3) & 1) * 8) * 2;

    // ---- per-thread state: ONE (cell, batch) pair per thread ----
    const int cc = tid & 15;                   // cell within group
    const int nb = tid >> 4;                   // local batch 0..31
    const int bglob = bbase + nb;
    const int cglob = cg * CPC + cc;
    const int p2 = ((cc >> 3) << 1) | (nb & 1);
    const int lane_src = ((cc & 7) << 2) | ((nb & 7) >> 1);
    const int wn_src = nb >> 3;
    const int aidx_base = wn_src * 32 + lane_src;

    float sn = n_in[bglob * C + cglob];
    float sd = d_in[bglob * C + cglob];
    float sa = amax_in[bglob * C + cglob];

    for (int t = 0; t < T; ++t) {
        const __nv_bfloat16* hhi = g_hshi + (size_t)t * BC;
        const __nv_bfloat16* hlo = g_hslo + (size_t)t * BC;
        const unsigned tgt = 16u * (unsigned)t;

        // epilogue-operand prefetch (DRAM, hidden under MMA loop)
        const size_t tb = (size_t)t * BC;
        const size_t eidx = tb + (size_t)bglob * C + cglob;
        float ax = __ldg(&g_AX[eidx]);
        float gx = __ldg(&g_GX[eidx]);
        float ux = __ldg(&g_U[eidx]);

        // ---- single wait: all 4 producer groups of step t-1 done ----
        if (tid == 0) {
            flag_wait4(&g_flag[bh][0], tgt);
            __threadfence();
        }
        __syncthreads();
        rec_load_chunk(rot, 0, sb, hhi, hlo, bbase, tid);

        float acc[8];
#pragma unroll
        for (int q = 0; q < 8; ++q) acc[q] = 0.f;

#pragma unroll 1
        for (int i = 0; i < NCH; ++i) {
            const int p = (rot + i) & 3;
            CPA_WAIT(0);
            __syncthreads();                   // other stage fully consumed
            if (i < NCH - 1)
                rec_load_chunk((rot + i + 1) & 3, (i + 1) & 1, sb, hhi, hlo,
                               bbase, tid);
            const uint32_t stg = sb + SB2(i & 1);
#pragma unroll
            for (int ks = 0; ks < 4; ++ks) {
                const int ka = p * CH + kq * 64 + ks * 16;
                const int kb = kq * 64 + ks * 16;
                uint32_t ah0[4], ah1[4], al0[4], al1[4], bf[4];
                ldm_x4(ah0, aHi0 + ka * 2);
                ldm_x4(ah1, aHi1 + ka * 2);
                ldm_x4(bf,  stg + bOffF + kb * 2);   // {bh, bl} fused
                ldm_x4(al0, aLo0 + ka * 2);
                ldm_x4(al1, aLo1 + ka * 2);
                mma16816(acc + 0, ah0, bf);
                mma16816(acc + 4, ah1, bf);
                mma16816(acc + 0, ah0, bf + 2);
                mma16816(acc + 4, ah1, bf + 2);
                mma16816(acc + 0, al0, bf);
                mma16816(acc + 4, al1, bf);
            }
        }

        // ---- all-warp partial dump, all-thread epilogue ----
        {
            float* dst = red + (kq * 8) * 128 + wn * 32 + lane;
#pragma unroll
            for (int q = 0; q < 8; ++q) dst[q * 128] = acc[q];
        }
        __syncthreads();
        {
            float at = ax, gt = gx;
#pragma unroll
            for (int k2 = 0; k2 < 4; ++k2) {
                at += red[(k2 * 8 + p2) * 128 + aidx_base];
                gt += red[(k2 * 8 + 4 + p2) * 128 + aidx_base];
            }
            float z  = ux * tanhf(gt);
            float an = fmaxf(sa, at);
            float ed = expf(sa - an);
            float es = expf(at - an);
            sn = sn * ed + z * es;
            sd = sd * ed + es;
            float h = tanhf(sn / sd);
            sa = an;
            __nv_bfloat16 hi, lo;
            split_bf16(h, hi, lo);
            g_hshi[(size_t)(t + 1) * BC + bglob * C + cglob] = hi;
            g_hslo[(size_t)(t + 1) * BC + bglob * C + cglob] = lo;
        }
        __threadfence();
        __syncthreads();
        if (tid == 0) atomicAdd(&g_flag[bh][rot], 1u);
    }

    out_n[bglob * C + cglob]    = sn;
    out_d[bglob * C + cglob]    = sd;
    out_h[bglob * C + cglob]    = tanhf(sn / sd);
    out_amax[bglob * C + cglob] = sa;
}

// ---------------- launch ---------------------------------------------------
extern "C" void kernel_launch(void* const* d_in, const int* in_sizes, int n_in,
                              void* d_out, int out_size) {
    (void)in_sizes; (void)n_in; (void)out_size;
    const float* x      = (const float*)d_in[0];
    const float* s      = (const float*)d_in[1];
    const float* n0     = (const float*)d_in[2];
    const float* d0     = (const float*)d_in[3];
    const float* h0     = (const float*)d_in[4];
    const float* amax0  = (const float*)d_in[5];
    const float* u_w    = (const float*)d_in[6];
    const float* u_b    = (const float*)d_in[7];
    const float* g_w    = (const float*)d_in[8];
    const float* g_b    = (const float*)d_in[9];
    const float* a_w    = (const float*)d_in[10];
    const float* o_w    = (const float*)d_in[11];
    const float* o_b    = (const float*)d_in[12];

    float* out        = (float*)d_out;
    float* out_outs   = out;
    float* out_s      = out + (size_t)B * T * KOUT;
    float* out_n      = out_s + C;
    float* out_d      = out_n + (size_t)B * C;
    float* out_h      = out_d + (size_t)B * C;
    float* out_amax   = out_h + (size_t)B * C;

    cudaFuncSetAttribute(rec_kernel, cudaFuncAttributeMaxDynamicSharedMemorySize, RSMEM);
    cudaFuncSetAttribute(pre_gemm_bf16, cudaFuncAttributeMaxDynamicSharedMemorySize, GSMEM);
    cudaFuncSetAttribute(out_gemm_bf16, cudaFuncAttributeMaxDynamicSharedMemorySize, GSMEM);

    wprep_rec<<<NCG * 32 * C / 256, 256>>>(g_w, a_w);
    xprep<<<(B * T * F) / 256, 256>>>(x);
    pwprep<<<(3 * C * F) / 256, 256>>>(u_w, g_w, a_w);
    owprep<<<(KOUT * C) / 256, 256>>>(o_w);
    hinit<<<(BC + 255) / 256, 256>>>(h0, s, out_s);
    pre_gemm_bf16<<<dim3(512, 48), 256, GSMEM>>>(u_b, g_b);
    rec_kernel<<<RCTA, RTHR, RSMEM>>>(n0, d0, amax0,
                                      out_n, out_d, out_h, out_amax);
    out_gemm_bf16<<<dim3(512, 4), 256, GSMEM>>>(o_b, out_outs);
}

// round 11
// speedup vs baseline: 1.5317x; 1.0264x over previous
#include <cuda_runtime.h>
#include <cuda_bf16.h>
#include <cstdint>

#define B 64
#define T 512
#define F 256
#define C 1024
#define KOUT 256
#define BC (B * C)
#define WROW (F + C)          // 1280 floats per g_w/a_w row

// ---------------- recurrent kernel config --------------------------------
#define RCTA 128              // (cg 0..63) x (batch-half 0..1)
#define NCG  64               // cell groups
#define RTHR 512              // 16 warps: kq = warp>>2, wn = warp&3
#define CPC  16               // cells per CTA  (A tile M = 32 = 16 a + 16 g)
#define NB   32               // batches per CTA
#define APITCH 1032           // smem A pitch (bf16)
#define BPITCH 136            // smem B pitch (bf16)
#define A_BYTES (64 * APITCH * 2)              // 132096
#define B_HALF  (NB * BPITCH * 2)              // 8704 per hi or lo tile
#define B_STAGE (2 * B_HALF)                   // 17408
#define NSTG 4
#define SB_OFF(s) (A_BYTES + (s) * B_STAGE)
#define RED_OFF (A_BYTES + NSTG * B_STAGE)     // 201728
#define RSMEM (RED_OFF + 16384)                // 218112

// ---------------- bf16 GEMM (pre/out) config -----------------------------
#define GP 72                                   // smem pitch (bf16)
#define GSTG (128 * GP * 2)                     // 18432 B per operand stage
#define GSTAGE (2 * GSTG)                       // 36864
#define GSMEM (3 * GSTAGE)                      // 110592

// ---------------- device scratch -----------------------------------------
__device__ __align__(16) float g_U [(size_t)T * BC];
__device__ __align__(16) float g_GX[(size_t)T * BC];
__device__ __align__(16) float g_AX[(size_t)T * BC];
__device__ __align__(16) __nv_bfloat16 g_hshi[(size_t)(T + 1) * BC]; // h slots
__device__ __align__(16) __nv_bfloat16 g_hslo[(size_t)(T + 1) * BC];
__device__ __align__(16) __nv_bfloat16 g_Awhi[NCG * 32 * C];  // rec weights
__device__ __align__(16) __nv_bfloat16 g_Awlo[NCG * 32 * C];
__device__ __align__(16) __nv_bfloat16 g_xhi[(size_t)B * T * F];
__device__ __align__(16) __nv_bfloat16 g_xlo[(size_t)B * T * F];
__device__ __align__(16) __nv_bfloat16 g_pwhi[3 * C * F];     // u/gF/aF rows
__device__ __align__(16) __nv_bfloat16 g_pwlo[3 * C * F];
__device__ __align__(16) __nv_bfloat16 g_owhi[KOUT * C];
__device__ __align__(16) __nv_bfloat16 g_owlo[KOUT * C];
__device__ __align__(32) unsigned g_flag[2][8];

// ---------------- helpers -------------------------------------------------
__device__ __forceinline__ uint32_t smem_u32(const void* p) {
    uint32_t a;
    asm("{ .reg .u64 t; cvta.to.shared.u64 t, %1; cvt.u32.u64 %0, t; }"
        : "=r"(a) : "l"(p));
    return a;
}
__device__ __forceinline__ void cpa16(uint32_t dst, const void* src) {
    asm volatile("cp.async.cg.shared.global [%0], [%1], 16;"
                 :: "r"(dst), "l"(src) : "memory");
}
#define CPA_COMMIT() asm volatile("cp.async.commit_group;" ::: "memory")
#define CPA_WAIT(n)  asm volatile("cp.async.wait_group %0;" :: "n"(n) : "memory")

__device__ __forceinline__ void mma16816(float* d, const uint32_t* a,
                                         const uint32_t* b) {
    asm volatile(
        "mma.sync.aligned.m16n8k16.row.col.f32.bf16.bf16.f32 "
        "{%0,%1,%2,%3},{%4,%5,%6,%7},{%8,%9},{%0,%1,%2,%3};"
        : "+f"(d[0]), "+f"(d[1]), "+f"(d[2]), "+f"(d[3])
        : "r"(a[0]), "r"(a[1]), "r"(a[2]), "r"(a[3]), "r"(b[0]), "r"(b[1]));
}
__device__ __forceinline__ void ldm_x4(uint32_t* r, uint32_t a) {
    asm volatile("ldmatrix.sync.aligned.m8n8.x4.shared.b16 {%0,%1,%2,%3}, [%4];"
                 : "=r"(r[0]), "=r"(r[1]), "=r"(r[2]), "=r"(r[3]) : "r"(a));
}
__device__ __forceinline__ void ldm_x2(uint32_t* r, uint32_t a) {
    asm volatile("ldmatrix.sync.aligned.m8n8.x2.shared.b16 {%0,%1}, [%2];"
                 : "=r"(r[0]), "=r"(r[1]) : "r"(a));
}
__device__ __forceinline__ void split_bf16(float v, __nv_bfloat16& hi,
                                           __nv_bfloat16& lo) {
    hi = __float2bfloat16_rn(v);
    lo = __float2bfloat16_rn(v - __bfloat162float(hi));
}
// poll all 8 producer flags with two volatile v4 loads; pure spin (1 thr/CTA)
__device__ __forceinline__ void flag_wait8(const unsigned* f, unsigned tgt) {
    for (;;) {
        unsigned a0, a1, a2, a3, b0, b1, b2, b3;
        asm volatile("ld.volatile.global.v4.u32 {%0,%1,%2,%3}, [%4];"
                     : "=r"(a0), "=r"(a1), "=r"(a2), "=r"(a3) : "l"(f));
        asm volatile("ld.volatile.global.v4.u32 {%0,%1,%2,%3}, [%4];"
                     : "=r"(b0), "=r"(b1), "=r"(b2), "=r"(b3) : "l"(f + 4));
        unsigned m = min(min(min(a0, a1), min(a2, a3)),
                         min(min(b0, b1), min(b2, b3)));
        if (m >= tgt) return;
    }
}

// ---------------- prep kernels -------------------------------------------
__global__ void wprep_rec(const float* __restrict__ g_w,
                          const float* __restrict__ a_w) {
    int idx = blockIdx.x * blockDim.x + threadIdx.x;   // NCG*32*C
    int cg = idx >> 15, r = (idx >> 10) & 31, k = idx & 1023;
    int cell = cg * CPC + (r & 15);
    const float* src = (r < 16) ? a_w : g_w;
    split_bf16(src[(size_t)cell * WROW + F + k], g_Awhi[idx], g_Awlo[idx]);
}
__global__ void xprep(const float* __restrict__ x) {
    size_t i = (size_t)blockIdx.x * blockDim.x + threadIdx.x;   // B*T*F
    split_bf16(x[i], g_xhi[i], g_xlo[i]);
}
__global__ void pwprep(const float* __restrict__ u_w,
                       const float* __restrict__ g_w,
                       const float* __restrict__ a_w) {
    int idx = blockIdx.x * blockDim.x + threadIdx.x;   // 3*C*F
    int row = idx >> 8, k = idx & 255;
    float v;
    if (row < C)           v = u_w[(size_t)row * F + k];
    else if (row < 2 * C)  v = g_w[(size_t)(row - C) * WROW + k];
    else                   v = a_w[(size_t)(row - 2 * C) * WROW + k];
    split_bf16(v, g_pwhi[idx], g_pwlo[idx]);
}
__global__ void owprep(const float* __restrict__ o_w) {
    int idx = blockIdx.x * blockDim.x + threadIdx.x;   // KOUT*C
    split_bf16(o_w[idx], g_owhi[idx], g_owlo[idx]);
}
__global__ void hinit(const float* __restrict__ h_in,
                      const float* __restrict__ s,
                      float* __restrict__ out_s) {
    int i = blockIdx.x * blockDim.x + threadIdx.x;
    if (i < BC) {
        int c = i & (C - 1);
        split_bf16(h_in[i] + tanhf(s[c]), g_hshi[i], g_hslo[i]);
    }
    if (i < C) out_s[i] = s[i];
    if (i < 16) ((unsigned*)g_flag)[i] = 0u;
}

// ---------------- generic bf16x3 GEMM bodies -----------------------------
struct GemmFrag {
    uint32_t aoff_h[2], aoff_l[2], boff_h[2], boff_l[2];
    int wm, wn, gid, tig, lane;
};
__device__ __forceinline__ GemmFrag gemm_frag(int tid) {
    GemmFrag f;
    int warp = tid >> 5;
    f.lane = tid & 31;
    f.gid = f.lane >> 2;
    f.tig = f.lane & 3;
    f.wm = warp & 1;
    f.wn = warp >> 1;
    int aRow = ((f.lane >> 3) & 1) * 8 + (f.lane & 7);
    int aCol = ((f.lane >> 4) & 1) * 8;
    int bRow = f.lane & 7;
    int bCol = ((f.lane >> 3) & 1) * 8;
#pragma unroll
    for (int mt = 0; mt < 2; ++mt) {
        f.aoff_h[mt] = (uint32_t)((f.wm * 32 + mt * 16 + aRow) * GP + aCol) * 2;
        f.aoff_l[mt] = (uint32_t)((64 + f.wm * 32 + mt * 16 + aRow) * GP + aCol) * 2;
    }
#pragma unroll
    for (int nt = 0; nt < 2; ++nt) {
        f.boff_h[nt] = (uint32_t)((f.wn * 16 + nt * 8 + bRow) * GP + bCol) * 2;
        f.boff_l[nt] = (uint32_t)((64 + f.wn * 16 + nt * 8 + bRow) * GP + bCol) * 2;
    }
    return f;
}
__device__ __forceinline__ void gemm_load_stage(
    uint32_t sb, int stg,
    const __nv_bfloat16* __restrict__ Ahi, const __nv_bfloat16* __restrict__ Alo,
    int lda,
    const __nv_bfloat16* __restrict__ Bhi, const __nv_bfloat16* __restrict__ Blo,
    int ldb, int k0, int tid) {
    uint32_t base = sb + stg * GSTAGE;
#pragma unroll
    for (int j = 0; j < 4; ++j) {
        int g = tid + j * 256;
        int row = g >> 3, q = g & 7;
        const __nv_bfloat16* src = (row < 64)
            ? Ahi + (size_t)row * lda + k0 + q * 8
            : Alo + (size_t)(row - 64) * lda + k0 + q * 8;
        cpa16(base + (uint32_t)(row * GP + q * 8) * 2, src);
    }
#pragma unroll
    for (int j = 0; j < 4; ++j) {
        int g = tid + j * 256;
        int row = g >> 3, q = g & 7;
        const __nv_bfloat16* src = (row < 64)
            ? Bhi + (size_t)row * ldb + k0 + q * 8
            : Blo + (size_t)(row - 64) * ldb + k0 + q * 8;
        cpa16(base + GSTG + (uint32_t)(row * GP + q * 8) * 2, src);
    }
    CPA_COMMIT();
}
__device__ __forceinline__ void gemm_mma_chunk(uint32_t sb, int stg,
                                               const GemmFrag& f,
                                               float acc[2][2][4]) {
    uint32_t stA = sb + stg * GSTAGE;
    uint32_t stB = stA + GSTG;
#pragma unroll
    for (int ks = 0; ks < 4; ++ks) {
        uint32_t kk = ks * 32;                 // bytes
        uint32_t ah[2][4], al[2][4], bh[2][2], bl[2][2];
#pragma unroll
        for (int mt = 0; mt < 2; ++mt) {
            ldm_x4(ah[mt], stA + f.aoff_h[mt] + kk);
            ldm_x4(al[mt], stA + f.aoff_l[mt] + kk);
        }
#pragma unroll
        for (int nt = 0; nt < 2; ++nt) {
            ldm_x2(bh[nt], stB + f.boff_h[nt] + kk);
            ldm_x2(bl[nt], stB + f.boff_l[nt] + kk);
        }
#pragma unroll
        for (int mt = 0; mt < 2; ++mt)
#pragma unroll
            for (int nt = 0; nt < 2; ++nt) {
                mma16816(acc[mt][nt], ah[mt], bh[nt]);
                mma16816(acc[mt][nt], ah[mt], bl[nt]);
                mma16816(acc[mt][nt], al[mt], bh[nt]);
            }
    }
}
__device__ __forceinline__ void gemm_transpose(char* smem, const GemmFrag& f,
                                               float acc[2][2][4]) {
    __syncthreads();
    float* tr = (float*)smem;                  // [n 64][m 64+4]
#pragma unroll
    for (int mt = 0; mt < 2; ++mt)
#pragma unroll
        for (int nt = 0; nt < 2; ++nt)
#pragma unroll
            for (int j = 0; j < 4; ++j) {
                int n = f.wn * 16 + nt * 8 + 2 * f.tig + (j & 1);
                int m = f.wm * 32 + mt * 16 + f.gid + (j >> 1) * 8;
                tr[n * 68 + m] = acc[mt][nt][j];
            }
    __syncthreads();
}

// ---------------- pre GEMM: [U|GX|AX] = x @ W^T + bias -------------------
__global__ void __launch_bounds__(256) pre_gemm_bf16(
    const float* __restrict__ u_b, const float* __restrict__ g_b) {
    extern __shared__ char smem[];
    const uint32_t sb = smem_u32(smem);
    const int tid = threadIdx.x;
    const int n0 = blockIdx.x * 64;            // x rows
    const int m0 = blockIdx.y * 64;            // weight rows (0..3071)
    const GemmFrag f = gemm_frag(tid);

    const __nv_bfloat16* Ahi = g_pwhi + (size_t)m0 * F;
    const __nv_bfloat16* Alo = g_pwlo + (size_t)m0 * F;
    const __nv_bfloat16* Bhi = g_xhi + (size_t)n0 * F;
    const __nv_bfloat16* Blo = g_xlo + (size_t)n0 * F;

    float acc[2][2][4] = {};
    const int NC = F / 64;                     // 4 chunks
    gemm_load_stage(sb, 0, Ahi, Alo, F, Bhi, Blo, F, 0, tid);
    gemm_load_stage(sb, 1, Ahi, Alo, F, Bhi, Blo, F, 64, tid);
    gemm_load_stage(sb, 2, Ahi, Alo, F, Bhi, Blo, F, 128, tid);
#pragma unroll 1
    for (int c = 0; c < NC; ++c) {
        int pend = NC - 1 - c;
        if (pend >= 2) CPA_WAIT(2); else if (pend == 1) CPA_WAIT(1); else CPA_WAIT(0);
        __syncthreads();
        gemm_mma_chunk(sb, c % 3, f, acc);
        if (c + 3 < NC) {
            __syncthreads();
            gemm_load_stage(sb, c % 3, Ahi, Alo, F, Bhi, Blo, F, (c + 3) * 64, tid);
        }
    }
    gemm_transpose(smem, f, acc);

    const int which = m0 >> 10;
    const int cbase = m0 & 1023;
    float* dst = (which == 0) ? g_U : (which == 1) ? g_GX : g_AX;
    const float* bias = (which == 0) ? u_b : (which == 1) ? g_b : nullptr;
    const float* tr = (const float*)smem;
    const int n = tid >> 2;
    const int n_g = n0 + n;
    const int b = n_g >> 9, t = n_g & 511;     // n_g = b*T + t
    float* drow = dst + (size_t)t * BC + (size_t)b * C + cbase;
#pragma unroll
    for (int q = 0; q < 4; ++q) {
        int m = ((tid & 3) * 4 + q) * 4;
        float4 v = *(const float4*)&tr[n * 68 + m];
        if (bias) {
            float4 bv = *(const float4*)&bias[cbase + m];
            v.x += bv.x; v.y += bv.y; v.z += bv.z; v.w += bv.w;
        }
        *(float4*)&drow[m] = v;
    }
}

// ---------------- out GEMM: outs[b][t][:] = h_t @ o_w^T + o_b ------------
__global__ void __launch_bounds__(256) out_gemm_bf16(
    const float* __restrict__ o_b, float* __restrict__ outp) {
    extern __shared__ char smem[];
    const uint32_t sb = smem_u32(smem);
    const int tid = threadIdx.x;
    const int tslot = blockIdx.x;              // t: h_t stored at slot t+1
    const int m0 = blockIdx.y * 64;            // out-class rows
    const GemmFrag f = gemm_frag(tid);

    const __nv_bfloat16* Ahi = g_owhi + (size_t)m0 * C;
    const __nv_bfloat16* Alo = g_owlo + (size_t)m0 * C;
    const __nv_bfloat16* Bhi = g_hshi + (size_t)(tslot + 1) * BC;
    const __nv_bfloat16* Blo = g_hslo + (size_t)(tslot + 1) * BC;

    float acc[2][2][4] = {};
    const int NC = C / 64;                     // 16 chunks
    gemm_load_stage(sb, 0, Ahi, Alo, C, Bhi, Blo, C, 0, tid);
    gemm_load_stage(sb, 1, Ahi, Alo, C, Bhi, Blo, C, 64, tid);
    gemm_load_stage(sb, 2, Ahi, Alo, C, Bhi, Blo, C, 128, tid);
#pragma unroll 1
    for (int c = 0; c < NC; ++c) {
        int pend = NC - 1 - c;
        if (pend >= 2) CPA_WAIT(2); else if (pend == 1) CPA_WAIT(1); else CPA_WAIT(0);
        __syncthreads();
        gemm_mma_chunk(sb, c % 3, f, acc);
        if (c + 3 < NC) {
            __syncthreads();
            gemm_load_stage(sb, c % 3, Ahi, Alo, C, Bhi, Blo, C, (c + 3) * 64, tid);
        }
    }
    gemm_transpose(smem, f, acc);

    const float* tr = (const float*)smem;
    const int b = tid >> 2;                    // n index = batch
    float* drow = outp + (size_t)b * T * KOUT + (size_t)tslot * KOUT + m0;
#pragma unroll
    for (int q = 0; q < 4; ++q) {
        int m = ((tid & 3) * 4 + q) * 4;
        float4 v = *(const float4*)&tr[b * 68 + m];
        float4 bv = *(const float4*)&o_b[m0 + m];
        v.x += bv.x; v.y += bv.y; v.z += bv.z; v.w += bv.w;
        *(float4*)&drow[m] = v;
    }
}

// ---------------- recurrent chunk loader (128k, 512 threads) -------------
__device__ __forceinline__ void rec_load_chunk(
    int p, int s, uint32_t sb, const __nv_bfloat16* __restrict__ hhi,
    const __nv_bfloat16* __restrict__ hlo, int bbase, int tid) {
#pragma unroll
    for (int j = 0; j < 2; ++j) {
        int i = tid + j * RTHR;                // 0..1023
        int half = i >> 9, r = (i >> 4) & 31, q = i & 15;
        uint32_t d = sb + SB_OFF(s) + half * B_HALF
                   + (uint32_t)(r * BPITCH) * 2 + q * 16;
        const __nv_bfloat16* src = (half ? hlo : hhi)
            + (size_t)(bbase + r) * C + p * 128 + q * 8;
        cpa16(d, src);
    }
    CPA_COMMIT();
}

// ---------------- persistent recurrent kernel (8x128, depth-3) -----------
__global__ void __launch_bounds__(RTHR, 1) rec_kernel(
    const float* __restrict__ n_in, const float* __restrict__ d_in,
    const float* __restrict__ amax_in,
    float* __restrict__ out_n, float* __restrict__ out_d,
    float* __restrict__ out_h, float* __restrict__ out_amax) {
    extern __shared__ char smem[];
    const uint32_t sb = smem_u32(smem);
    float* red = (float*)(smem + RED_OFF);     // [4 kq][8 q][128]

    const int tid   = threadIdx.x;
    const int warp  = tid >> 5;
    const int lane  = tid & 31;
    const int wn    = warp & 3;                // n-tile: batches wn*8..+7
    const int kq    = warp >> 2;               // k-quarter (32) within chunk
    const int cg    = blockIdx.x >> 1;
    const int bh    = blockIdx.x & 1;
    const int bbase = bh * NB;
    const int rot   = cg >> 3;                 // starting chunk (0..7)

    // ---- prologue: resident weights into smem ----
    for (int i = tid; i < 64 * 128; i += RTHR) {
        int row = i >> 7, q = i & 127;
        const __nv_bfloat16* src = (row < 32)
            ? g_Awhi + ((size_t)cg * 32 + row) * C + q * 8
            : g_Awlo + ((size_t)cg * 32 + row - 32) * C + q * 8;
        cpa16(sb + (uint32_t)(row * APITCH + q * 8) * 2, src);
    }
    CPA_COMMIT();

    const int aRow = ((lane >> 3) & 1) * 8 + (lane & 7);
    const int aCol = ((lane >> 4) & 1) * 8;
    const uint32_t aHi0 = sb + (uint32_t)((aRow)      * APITCH + aCol) * 2;
    const uint32_t aHi1 = sb + (uint32_t)((16 + aRow) * APITCH + aCol) * 2;
    const uint32_t aLo0 = sb + (uint32_t)((32 + aRow) * APITCH + aCol) * 2;
    const uint32_t aLo1 = sb + (uint32_t)((48 + aRow) * APITCH + aCol) * 2;
    // fused B x4: lanes 0-15 -> Bhi tile, lanes 16-31 -> Blo tile
    const uint32_t bOffF = (uint32_t)(lane >> 4) * B_HALF
        + (uint32_t)((wn * 8 + (lane & 7)) * BPITCH + ((lane >> 3) & 1) * 8) * 2;

    // ---- per-thread state: ONE (cell, batch) pair per thread ----
    const int cc = tid & 15;                   // cell within group
    const int nb = tid >> 4;                   // local batch 0..31
    const int bglob = bbase + nb;
    const int cglob = cg * CPC + cc;
    const int p2 = ((cc >> 3) << 1) | (nb & 1);
    const int lane_src = ((cc & 7) << 2) | ((nb & 7) >> 1);
    const int wn_src = nb >> 3;
    const int aidx_base = wn_src * 32 + lane_src;

    float sn = n_in[bglob * C + cglob];
    float sd = d_in[bglob * C + cglob];
    float sa = amax_in[bglob * C + cglob];

    for (int t = 0; t < T; ++t) {
        const __nv_bfloat16* hhi = g_hshi + (size_t)t * BC;
        const __nv_bfloat16* hlo = g_hslo + (size_t)t * BC;
        const unsigned tgt = 8u * (unsigned)t;

        // epilogue-operand prefetch (DRAM, hidden under MMA loop)
        const size_t tb = (size_t)t * BC;
        const size_t eidx = tb + (size_t)bglob * C + cglob;
        float ax = __ldg(&g_AX[eidx]);
        float gx = __ldg(&g_GX[eidx]);
        float ux = __ldg(&g_U[eidx]);

        // ---- single wait: all 8 producer groups of step t-1 done ----
        if (tid == 0) {
            flag_wait8(&g_flag[bh][0], tgt);
            __threadfence();
        }
        __syncthreads();
        rec_load_chunk(rot, 0, sb, hhi, hlo, bbase, tid);
        rec_load_chunk((rot + 1) & 7, 1, sb, hhi, hlo, bbase, tid);
        rec_load_chunk((rot + 2) & 7, 2, sb, hhi, hlo, bbase, tid);

        float acc[8];
#pragma unroll
        for (int q = 0; q < 8; ++q) acc[q] = 0.f;

#pragma unroll 1
        for (int i = 0; i < 8; ++i) {
            const int p = (rot + i) & 7;
            if (i <= 5) CPA_WAIT(2);
            else if (i == 6) CPA_WAIT(1);
            else CPA_WAIT(0);
            __syncthreads();                   // stage (i+3)&3 consumed at i-1
            if (i < 5)
                rec_load_chunk((rot + i + 3) & 7, (i + 3) & 3, sb, hhi, hlo,
                               bbase, tid);
            const uint32_t stg = sb + SB_OFF(i & 3);
#pragma unroll
            for (int ks = 0; ks < 2; ++ks) {
                const int ka = p * 128 + kq * 32 + ks * 16;
                const int kb = kq * 32 + ks * 16;
                uint32_t ah0[4], ah1[4], al0[4], al1[4], bf[4];
                ldm_x4(ah0, aHi0 + ka * 2);
                ldm_x4(ah1, aHi1 + ka * 2);
                ldm_x4(bf,  stg + bOffF + kb * 2);   // {bh, bl} fused
                ldm_x4(al0, aLo0 + ka * 2);
                ldm_x4(al1, aLo1 + ka * 2);
                mma16816(acc + 0, ah0, bf);
                mma16816(acc + 4, ah1, bf);
                mma16816(acc + 0, ah0, bf + 2);
                mma16816(acc + 4, ah1, bf + 2);
                mma16816(acc + 0, al0, bf);
                mma16816(acc + 4, al1, bf);
            }
        }

        // ---- all-warp partial dump, all-thread epilogue ----
        {
            float* dst = red + (kq * 8) * 128 + wn * 32 + lane;
#pragma unroll
            for (int q = 0; q < 8; ++q) dst[q * 128] = acc[q];
        }
        __syncthreads();
        {
            float at = ax, gt = gx;
#pragma unroll
            for (int k2 = 0; k2 < 4; ++k2) {
                at += red[(k2 * 8 + p2) * 128 + aidx_base];
                gt += red[(k2 * 8 + 4 + p2) * 128 + aidx_base];
            }
            float z  = ux * tanhf(gt);
            float an = fmaxf(sa, at);
            float ed = expf(sa - an);
            float es = expf(at - an);
            sn = sn * ed + z * es;
            sd = sd * ed + es;
            float h = tanhf(sn / sd);
            sa = an;
            __nv_bfloat16 hi, lo;
            split_bf16(h, hi, lo);
            g_hshi[(size_t)(t + 1) * BC + bglob * C + cglob] = hi;
            g_hslo[(size_t)(t + 1) * BC + bglob * C + cglob] = lo;
        }
        __syncthreads();                       // h stores done CTA-wide
        if (tid == 0) {                        // barrier + 1-thread fence
            __threadfence();
            atomicAdd(&g_flag[bh][rot], 1u);
        }
    }

    out_n[bglob * C + cglob]    = sn;
    out_d[bglob * C + cglob]    = sd;
    out_h[bglob * C + cglob]    = tanhf(sn / sd);
    out_amax[bglob * C + cglob] = sa;
}

// ---------------- launch ---------------------------------------------------
extern "C" void kernel_launch(void* const* d_in, const int* in_sizes, int n_in,
                              void* d_out, int out_size) {
    (void)in_sizes; (void)n_in; (void)out_size;
    const float* x      = (const float*)d_in[0];
    const float* s      = (const float*)d_in[1];
    const float* n0     = (const float*)d_in[2];
    const float* d0     = (const float*)d_in[3];
    const float* h0     = (const float*)d_in[4];
    const float* amax0  = (const float*)d_in[5];
    const float* u_w    = (const float*)d_in[6];
    const float* u_b    = (const float*)d_in[7];
    const float* g_w    = (const float*)d_in[8];
    const float* g_b    = (const float*)d_in[9];
    const float* a_w    = (const float*)d_in[10];
    const float* o_w    = (const float*)d_in[11];
    const float* o_b    = (const float*)d_in[12];

    float* out        = (float*)d_out;
    float* out_outs   = out;
    float* out_s      = out + (size_t)B * T * KOUT;
    float* out_n      = out_s + C;
    float* out_d      = out_n + (size_t)B * C;
    float* out_h      = out_d + (size_t)B * C;
    float* out_amax   = out_h + (size_t)B * C;

    cudaFuncSetAttribute(rec_kernel, cudaFuncAttributeMaxDynamicSharedMemorySize, RSMEM);
    cudaFuncSetAttribute(pre_gemm_bf16, cudaFuncAttributeMaxDynamicSharedMemorySize, GSMEM);
    cudaFuncSetAttribute(out_gemm_bf16, cudaFuncAttributeMaxDynamicSharedMemorySize, GSMEM);

    wprep_rec<<<NCG * 32 * C / 256, 256>>>(g_w, a_w);
    xprep<<<(B * T * F) / 256, 256>>>(x);
    pwprep<<<(3 * C * F) / 256, 256>>>(u_w, g_w, a_w);
    owprep<<<(KOUT * C) / 256, 256>>>(o_w);
    hinit<<<(BC + 255) / 256, 256>>>(h0, s, out_s);
    pre_gemm_bf16<<<dim3(512, 48), 256, GSMEM>>>(u_b, g_b);
    rec_kernel<<<RCTA, RTHR, RSMEM>>>(n0, d0, amax0,
                                      out_n, out_d, out_h, out_amax);
    out_gemm_bf16<<<dim3(512, 4), 256, GSMEM>>>(o_b, out_outs);
}

// round 12
// speedup vs baseline: 1.6170x; 1.0557x over previous
#include <cuda_runtime.h>
#include <cuda_bf16.h>
#include <cstdint>

#define B 64
#define T 512
#define F 256
#define C 1024
#define KOUT 256
#define BC (B * C)
#define WROW (F + C)          // 1280 floats per g_w/a_w row

// ---------------- recurrent kernel config --------------------------------
#define RCTA 128              // (cg 0..63) x (batch-half 0..1)
#define NCG  64               // cell groups
#define RTHR 512              // 16 warps: kq = warp>>2, wn = warp&3
#define CPC  16               // cells per CTA  (A tile M = 32 = 16 a + 16 g)
#define NB   32               // batches per CTA
#define APITCH 1032           // smem A pitch (bf16)
#define A_BYTES (64 * APITCH * 2)              // 132096
// warp-private B ring: 3 stages x 1280 B (2 halves x 8 rows x 80 B)
#define WB_STG 1280
#define WB_WARP (3 * WB_STG)                   // 3840
#define WB_OFF A_BYTES
#define RED_OFF (WB_OFF + 16 * WB_WARP)        // 193536
#define RSMEM (RED_OFF + 16384)                // 209920

// ---------------- bf16 GEMM (pre/out) config -----------------------------
#define GP 72                                   // smem pitch (bf16)
#define GSTG (128 * GP * 2)                     // 18432 B per operand stage
#define GSTAGE (2 * GSTG)                       // 36864
#define GSMEM (3 * GSTAGE)                      // 110592

// ---------------- device scratch -----------------------------------------
__device__ __align__(16) float g_U [(size_t)T * BC];
__device__ __align__(16) float g_GX[(size_t)T * BC];
__device__ __align__(16) float g_AX[(size_t)T * BC];
__device__ __align__(16) __nv_bfloat16 g_hshi[(size_t)(T + 1) * BC]; // h slots
__device__ __align__(16) __nv_bfloat16 g_hslo[(size_t)(T + 1) * BC];
__device__ __align__(16) __nv_bfloat16 g_Awhi[NCG * 32 * C];  // rec weights
__device__ __align__(16) __nv_bfloat16 g_Awlo[NCG * 32 * C];
__device__ __align__(16) __nv_bfloat16 g_xhi[(size_t)B * T * F];
__device__ __align__(16) __nv_bfloat16 g_xlo[(size_t)B * T * F];
__device__ __align__(16) __nv_bfloat16 g_pwhi[3 * C * F];     // u/gF/aF rows
__device__ __align__(16) __nv_bfloat16 g_pwlo[3 * C * F];
__device__ __align__(16) __nv_bfloat16 g_owhi[KOUT * C];
__device__ __align__(16) __nv_bfloat16 g_owlo[KOUT * C];
__device__ __align__(32) unsigned g_flag[2][8];

// ---------------- helpers -------------------------------------------------
__device__ __forceinline__ uint32_t smem_u32(const void* p) {
    uint32_t a;
    asm("{ .reg .u64 t; cvta.to.shared.u64 t, %1; cvt.u32.u64 %0, t; }"
        : "=r"(a) : "l"(p));
    return a;
}
__device__ __forceinline__ void cpa16(uint32_t dst, const void* src) {
    asm volatile("cp.async.cg.shared.global [%0], [%1], 16;"
                 :: "r"(dst), "l"(src) : "memory");
}
#define CPA_COMMIT() asm volatile("cp.async.commit_group;" ::: "memory")
#define CPA_WAIT(n)  asm volatile("cp.async.wait_group %0;" :: "n"(n) : "memory")

__device__ __forceinline__ void mma16816(float* d, const uint32_t* a,
                                         const uint32_t* b) {
    asm volatile(
        "mma.sync.aligned.m16n8k16.row.col.f32.bf16.bf16.f32 "
        "{%0,%1,%2,%3},{%4,%5,%6,%7},{%8,%9},{%0,%1,%2,%3};"
        : "+f"(d[0]), "+f"(d[1]), "+f"(d[2]), "+f"(d[3])
        : "r"(a[0]), "r"(a[1]), "r"(a[2]), "r"(a[3]), "r"(b[0]), "r"(b[1]));
}
__device__ __forceinline__ void ldm_x4(uint32_t* r, uint32_t a) {
    asm volatile("ldmatrix.sync.aligned.m8n8.x4.shared.b16 {%0,%1,%2,%3}, [%4];"
                 : "=r"(r[0]), "=r"(r[1]), "=r"(r[2]), "=r"(r[3]) : "r"(a));
}
__device__ __forceinline__ void ldm_x2(uint32_t* r, uint32_t a) {
    asm volatile("ldmatrix.sync.aligned.m8n8.x2.shared.b16 {%0,%1}, [%2];"
                 : "=r"(r[0]), "=r"(r[1]) : "r"(a));
}
__device__ __forceinline__ void split_bf16(float v, __nv_bfloat16& hi,
                                           __nv_bfloat16& lo) {
    hi = __float2bfloat16_rn(v);
    lo = __float2bfloat16_rn(v - __bfloat162float(hi));
}
// poll all 8 producer flags with two volatile v4 loads; pure spin (1 thr/CTA)
__device__ __forceinline__ void flag_wait8(const unsigned* f, unsigned tgt) {
    for (;;) {
        unsigned a0, a1, a2, a3, b0, b1, b2, b3;
        asm volatile("ld.volatile.global.v4.u32 {%0,%1,%2,%3}, [%4];"
                     : "=r"(a0), "=r"(a1), "=r"(a2), "=r"(a3) : "l"(f));
        asm volatile("ld.volatile.global.v4.u32 {%0,%1,%2,%3}, [%4];"
                     : "=r"(b0), "=r"(b1), "=r"(b2), "=r"(b3) : "l"(f + 4));
        unsigned m = min(min(min(a0, a1), min(a2, a3)),
                         min(min(b0, b1), min(b2, b3)));
        if (m >= tgt) return;
    }
}

// ---------------- prep kernels -------------------------------------------
__global__ void wprep_rec(const float* __restrict__ g_w,
                          const float* __restrict__ a_w) {
    int idx = blockIdx.x * blockDim.x + threadIdx.x;   // NCG*32*C
    int cg = idx >> 15, r = (idx >> 10) & 31, k = idx & 1023;
    int cell = cg * CPC + (r & 15);
    const float* src = (r < 16) ? a_w : g_w;
    split_bf16(src[(size_t)cell * WROW + F + k], g_Awhi[idx], g_Awlo[idx]);
}
__global__ void xprep(const float* __restrict__ x) {
    size_t i = (size_t)blockIdx.x * blockDim.x + threadIdx.x;   // B*T*F
    split_bf16(x[i], g_xhi[i], g_xlo[i]);
}
__global__ void pwprep(const float* __restrict__ u_w,
                       const float* __restrict__ g_w,
                       const float* __restrict__ a_w) {
    int idx = blockIdx.x * blockDim.x + threadIdx.x;   // 3*C*F
    int row = idx >> 8, k = idx & 255;
    float v;
    if (row < C)           v = u_w[(size_t)row * F + k];
    else if (row < 2 * C)  v = g_w[(size_t)(row - C) * WROW + k];
    else                   v = a_w[(size_t)(row - 2 * C) * WROW + k];
    split_bf16(v, g_pwhi[idx], g_pwlo[idx]);
}
__global__ void owprep(const float* __restrict__ o_w) {
    int idx = blockIdx.x * blockDim.x + threadIdx.x;   // KOUT*C
    split_bf16(o_w[idx], g_owhi[idx], g_owlo[idx]);
}
__global__ void hinit(const float* __restrict__ h_in,
                      const float* __restrict__ s,
                      float* __restrict__ out_s) {
    int i = blockIdx.x * blockDim.x + threadIdx.x;
    if (i < BC) {
        int c = i & (C - 1);
        split_bf16(h_in[i] + tanhf(s[c]), g_hshi[i], g_hslo[i]);
    }
    if (i < C) out_s[i] = s[i];
    if (i < 16) ((unsigned*)g_flag)[i] = 0u;
}

// ---------------- generic bf16x3 GEMM bodies -----------------------------
struct GemmFrag {
    uint32_t aoff_h[2], aoff_l[2], boff_h[2], boff_l[2];
    int wm, wn, gid, tig, lane;
};
__device__ __forceinline__ GemmFrag gemm_frag(int tid) {
    GemmFrag f;
    int warp = tid >> 5;
    f.lane = tid & 31;
    f.gid = f.lane >> 2;
    f.tig = f.lane & 3;
    f.wm = warp & 1;
    f.wn = warp >> 1;
    int aRow = ((f.lane >> 3) & 1) * 8 + (f.lane & 7);
    int aCol = ((f.lane >> 4) & 1) * 8;
    int bRow = f.lane & 7;
    int bCol = ((f.lane >> 3) & 1) * 8;
#pragma unroll
    for (int mt = 0; mt < 2; ++mt) {
        f.aoff_h[mt] = (uint32_t)((f.wm * 32 + mt * 16 + aRow) * GP + aCol) * 2;
        f.aoff_l[mt] = (uint32_t)((64 + f.wm * 32 + mt * 16 + aRow) * GP + aCol) * 2;
    }
#pragma unroll
    for (int nt = 0; nt < 2; ++nt) {
        f.boff_h[nt] = (uint32_t)((f.wn * 16 + nt * 8 + bRow) * GP + bCol) * 2;
        f.boff_l[nt] = (uint32_t)((64 + f.wn * 16 + nt * 8 + bRow) * GP + bCol) * 2;
    }
    return f;
}
__device__ __forceinline__ void gemm_load_stage(
    uint32_t sb, int stg,
    const __nv_bfloat16* __restrict__ Ahi, const __nv_bfloat16* __restrict__ Alo,
    int lda,
    const __nv_bfloat16* __restrict__ Bhi, const __nv_bfloat16* __restrict__ Blo,
    int ldb, int k0, int tid) {
    uint32_t base = sb + stg * GSTAGE;
#pragma unroll
    for (int j = 0; j < 4; ++j) {
        int g = tid + j * 256;
        int row = g >> 3, q = g & 7;
        const __nv_bfloat16* src = (row < 64)
            ? Ahi + (size_t)row * lda + k0 + q * 8
            : Alo + (size_t)(row - 64) * lda + k0 + q * 8;
        cpa16(base + (uint32_t)(row * GP + q * 8) * 2, src);
    }
#pragma unroll
    for (int j = 0; j < 4; ++j) {
        int g = tid + j * 256;
        int row = g >> 3, q = g & 7;
        const __nv_bfloat16* src = (row < 64)
            ? Bhi + (size_t)row * ldb + k0 + q * 8
            : Blo + (size_t)(row - 64) * ldb + k0 + q * 8;
        cpa16(base + GSTG + (uint32_t)(row * GP + q * 8) * 2, src);
    }
    CPA_COMMIT();
}
__device__ __forceinline__ void gemm_mma_chunk(uint32_t sb, int stg,
                                               const GemmFrag& f,
                                               float acc[2][2][4]) {
    uint32_t stA = sb + stg * GSTAGE;
    uint32_t stB = stA + GSTG;
#pragma unroll
    for (int ks = 0; ks < 4; ++ks) {
        uint32_t kk = ks * 32;                 // bytes
        uint32_t ah[2][4], al[2][4], bh[2][2], bl[2][2];
#pragma unroll
        for (int mt = 0; mt < 2; ++mt) {
            ldm_x4(ah[mt], stA + f.aoff_h[mt] + kk);
            ldm_x4(al[mt], stA + f.aoff_l[mt] + kk);
        }
#pragma unroll
        for (int nt = 0; nt < 2; ++nt) {
            ldm_x2(bh[nt], stB + f.boff_h[nt] + kk);
            ldm_x2(bl[nt], stB + f.boff_l[nt] + kk);
        }
#pragma unroll
        for (int mt = 0; mt < 2; ++mt)
#pragma unroll
            for (int nt = 0; nt < 2; ++nt) {
                mma16816(acc[mt][nt], ah[mt], bh[nt]);
                mma16816(acc[mt][nt], ah[mt], bl[nt]);
                mma16816(acc[mt][nt], al[mt], bh[nt]);
            }
    }
}
__device__ __forceinline__ void gemm_transpose(char* smem, const GemmFrag& f,
                                               float acc[2][2][4]) {
    __syncthreads();
    float* tr = (float*)smem;                  // [n 64][m 64+4]
#pragma unroll
    for (int mt = 0; mt < 2; ++mt)
#pragma unroll
        for (int nt = 0; nt < 2; ++nt)
#pragma unroll
            for (int j = 0; j < 4; ++j) {
                int n = f.wn * 16 + nt * 8 + 2 * f.tig + (j & 1);
                int m = f.wm * 32 + mt * 16 + f.gid + (j >> 1) * 8;
                tr[n * 68 + m] = acc[mt][nt][j];
            }
    __syncthreads();
}

// ---------------- pre GEMM: [U|GX|AX] = x @ W^T + bias -------------------
__global__ void __launch_bounds__(256) pre_gemm_bf16(
    const float* __restrict__ u_b, const float* __restrict__ g_b) {
    extern __shared__ char smem[];
    const uint32_t sb = smem_u32(smem);
    const int tid = threadIdx.x;
    const int n0 = blockIdx.x * 64;            // x rows
    const int m0 = blockIdx.y * 64;            // weight rows (0..3071)
    const GemmFrag f = gemm_frag(tid);

    const __nv_bfloat16* Ahi = g_pwhi + (size_t)m0 * F;
    const __nv_bfloat16* Alo = g_pwlo + (size_t)m0 * F;
    const __nv_bfloat16* Bhi = g_xhi + (size_t)n0 * F;
    const __nv_bfloat16* Blo = g_xlo + (size_t)n0 * F;

    float acc[2][2][4] = {};
    const int NC = F / 64;                     // 4 chunks
    gemm_load_stage(sb, 0, Ahi, Alo, F, Bhi, Blo, F, 0, tid);
    gemm_load_stage(sb, 1, Ahi, Alo, F, Bhi, Blo, F, 64, tid);
    gemm_load_stage(sb, 2, Ahi, Alo, F, Bhi, Blo, F, 128, tid);
#pragma unroll 1
    for (int c = 0; c < NC; ++c) {
        int pend = NC - 1 - c;
        if (pend >= 2) CPA_WAIT(2); else if (pend == 1) CPA_WAIT(1); else CPA_WAIT(0);
        __syncthreads();
        gemm_mma_chunk(sb, c % 3, f, acc);
        if (c + 3 < NC) {
            __syncthreads();
            gemm_load_stage(sb, c % 3, Ahi, Alo, F, Bhi, Blo, F, (c + 3) * 64, tid);
        }
    }
    gemm_transpose(smem, f, acc);

    const int which = m0 >> 10;
    const int cbase = m0 & 1023;
    float* dst = (which == 0) ? g_U : (which == 1) ? g_GX : g_AX;
    const float* bias = (which == 0) ? u_b : (which == 1) ? g_b : nullptr;
    const float* tr = (const float*)smem;
    const int n = tid >> 2;
    const int n_g = n0 + n;
    const int b = n_g >> 9, t = n_g & 511;     // n_g = b*T + t
    float* drow = dst + (size_t)t * BC + (size_t)b * C + cbase;
#pragma unroll
    for (int q = 0; q < 4; ++q) {
        int m = ((tid & 3) * 4 + q) * 4;
        float4 v = *(const float4*)&tr[n * 68 + m];
        if (bias) {
            float4 bv = *(const float4*)&bias[cbase + m];
            v.x += bv.x; v.y += bv.y; v.z += bv.z; v.w += bv.w;
        }
        *(float4*)&drow[m] = v;
    }
}

// ---------------- out GEMM: outs[b][t][:] = h_t @ o_w^T + o_b ------------
__global__ void __launch_bounds__(256) out_gemm_bf16(
    const float* __restrict__ o_b, float* __restrict__ outp) {
    extern __shared__ char smem[];
    const uint32_t sb = smem_u32(smem);
    const int tid = threadIdx.x;
    const int tslot = blockIdx.x;              // t: h_t stored at slot t+1
    const int m0 = blockIdx.y * 64;            // out-class rows
    const GemmFrag f = gemm_frag(tid);

    const __nv_bfloat16* Ahi = g_owhi + (size_t)m0 * C;
    const __nv_bfloat16* Alo = g_owlo + (size_t)m0 * C;
    const __nv_bfloat16* Bhi = g_hshi + (size_t)(tslot + 1) * BC;
    const __nv_bfloat16* Blo = g_hslo + (size_t)(tslot + 1) * BC;

    float acc[2][2][4] = {};
    const int NC = C / 64;                     // 16 chunks
    gemm_load_stage(sb, 0, Ahi, Alo, C, Bhi, Blo, C, 0, tid);
    gemm_load_stage(sb, 1, Ahi, Alo, C, Bhi, Blo, C, 64, tid);
    gemm_load_stage(sb, 2, Ahi, Alo, C, Bhi, Blo, C, 128, tid);
#pragma unroll 1
    for (int c = 0; c < NC; ++c) {
        int pend = NC - 1 - c;
        if (pend >= 2) CPA_WAIT(2); else if (pend == 1) CPA_WAIT(1); else CPA_WAIT(0);
        __syncthreads();
        gemm_mma_chunk(sb, c % 3, f, acc);
        if (c + 3 < NC) {
            __syncthreads();
            gemm_load_stage(sb, c % 3, Ahi, Alo, C, Bhi, Blo, C, (c + 3) * 64, tid);
        }
    }
    gemm_transpose(smem, f, acc);

    const float* tr = (const float*)smem;
    const int b = tid >> 2;                    // n index = batch
    float* drow = outp + (size_t)b * T * KOUT + (size_t)tslot * KOUT + m0;
#pragma unroll
    for (int q = 0; q < 4; ++q) {
        int m = ((tid & 3) * 4 + q) * 4;
        float4 v = *(const float4*)&tr[b * 68 + m];
        float4 bv = *(const float4*)&o_b[m0 + m];
        v.x += bv.x; v.y += bv.y; v.z += bv.z; v.w += bv.w;
        *(float4*)&drow[m] = v;
    }
}

// ---------------- warp-private B slice loader ----------------------------
// Each warp loads ONLY its (wn, kq) slice: 8 rows x 32 cols, hi+lo = 1 KB.
// 64 pieces of 16 B; 2 per lane. Row pitch 80 B (conflict-free ldmatrix).
__device__ __forceinline__ void rec_load_my(
    int p, int s, uint32_t wb, const __nv_bfloat16* __restrict__ hhi,
    const __nv_bfloat16* __restrict__ hlo, int bbase, int wn, int kq,
    int lane) {
#pragma unroll
    for (int j = 0; j < 2; ++j) {
        int i = lane * 2 + j;                  // 0..63
        int half = i >> 5, r = (i >> 2) & 7, q = i & 3;
        uint32_t d = wb + s * WB_STG + half * 640 + r * 80 + q * 16;
        const __nv_bfloat16* src = (half ? hlo : hhi)
            + (size_t)(bbase + wn * 8 + r) * C + p * 128 + kq * 32 + q * 8;
        cpa16(d, src);
    }
    CPA_COMMIT();
}

// ---------------- persistent recurrent kernel (barrier-free k-loop) ------
__global__ void __launch_bounds__(RTHR, 1) rec_kernel(
    const float* __restrict__ n_in, const float* __restrict__ d_in,
    const float* __restrict__ amax_in,
    float* __restrict__ out_n, float* __restrict__ out_d,
    float* __restrict__ out_h, float* __restrict__ out_amax) {
    extern __shared__ char smem[];
    const uint32_t sb = smem_u32(smem);
    float* red = (float*)(smem + RED_OFF);     // [4 kq][8 q][128]

    const int tid   = threadIdx.x;
    const int warp  = tid >> 5;
    const int lane  = tid & 31;
    const int wn    = warp & 3;                // n-tile: batches wn*8..+7
    const int kq    = warp >> 2;               // k-quarter (32) within chunk
    const int cg    = blockIdx.x >> 1;
    const int bh    = blockIdx.x & 1;
    const int bbase = bh * NB;
    const int rot   = cg >> 3;                 // starting chunk (0..7)
    const uint32_t wb = sb + WB_OFF + warp * WB_WARP;

    // ---- prologue: resident weights into smem (CTA-shared, once) ----
    for (int i = tid; i < 64 * 128; i += RTHR) {
        int row = i >> 7, q = i & 127;
        const __nv_bfloat16* src = (row < 32)
            ? g_Awhi + ((size_t)cg * 32 + row) * C + q * 8
            : g_Awlo + ((size_t)cg * 32 + row - 32) * C + q * 8;
        cpa16(sb + (uint32_t)(row * APITCH + q * 8) * 2, src);
    }
    CPA_COMMIT();
    CPA_WAIT(0);
    __syncthreads();                           // A tile visible to all warps

    const int aRow = ((lane >> 3) & 1) * 8 + (lane & 7);
    const int aCol = ((lane >> 4) & 1) * 8;
    const uint32_t aHi0 = sb + (uint32_t)((aRow)      * APITCH + aCol) * 2;
    const uint32_t aHi1 = sb + (uint32_t)((16 + aRow) * APITCH + aCol) * 2;
    const uint32_t aLo0 = sb + (uint32_t)((32 + aRow) * APITCH + aCol) * 2;
    const uint32_t aLo1 = sb + (uint32_t)((48 + aRow) * APITCH + aCol) * 2;
    // fused B x4 from warp-private ring: lanes 0-15 hi, 16-31 lo
    const uint32_t bBase = wb + (uint32_t)(lane >> 4) * 640
                         + (uint32_t)(lane & 7) * 80
                         + (uint32_t)((lane >> 3) & 1) * 16;

    // ---- per-thread state: ONE (cell, batch) pair per thread ----
    const int cc = tid & 15;                   // cell within group
    const int nb = tid >> 4;                   // local batch 0..31
    const int bglob = bbase + nb;
    const int cglob = cg * CPC + cc;
    const int p2 = ((cc >> 3) << 1) | (nb & 1);
    const int lane_src = ((cc & 7) << 2) | ((nb & 7) >> 1);
    const int wn_src = nb >> 3;
    const int aidx_base = wn_src * 32 + lane_src;

    float sn = n_in[bglob * C + cglob];
    float sd = d_in[bglob * C + cglob];
    float sa = amax_in[bglob * C + cglob];

    for (int t = 0; t < T; ++t) {
        const __nv_bfloat16* hhi = g_hshi + (size_t)t * BC;
        const __nv_bfloat16* hlo = g_hslo + (size_t)t * BC;
        const unsigned tgt = 8u * (unsigned)t;

        // epilogue-operand prefetch (DRAM, hidden under MMA loop)
        const size_t tb = (size_t)t * BC;
        const size_t eidx = tb + (size_t)bglob * C + cglob;
        float ax = __ldg(&g_AX[eidx]);
        float gx = __ldg(&g_GX[eidx]);
        float ux = __ldg(&g_U[eidx]);

        // ---- single wait: all 8 producer groups of step t-1 done ----
        if (tid == 0) {
            flag_wait8(&g_flag[bh][0], tgt);
            __threadfence();
        }
        __syncthreads();

        // per-warp pipeline: 2 chunks in flight, private buffers
        rec_load_my(rot, 0, wb, hhi, hlo, bbase, wn, kq, lane);
        rec_load_my((rot + 1) & 7, 1, wb, hhi, hlo, bbase, wn, kq, lane);

        float acc[8];
#pragma unroll
        for (int q = 0; q < 8; ++q) acc[q] = 0.f;

#pragma unroll 1
        for (int i = 0; i < 8; ++i) {
            const int p = (rot + i) & 7;
            if (i < 7) CPA_WAIT(1); else CPA_WAIT(0);   // thread-scoped
            if (i < 6)
                rec_load_my((rot + i + 2) & 7, (i + 2) % 3, wb, hhi, hlo,
                            bbase, wn, kq, lane);
            const uint32_t bs = bBase + (uint32_t)((i % 3) * WB_STG);
#pragma unroll
            for (int ks = 0; ks < 2; ++ks) {
                const int ka = p * 128 + kq * 32 + ks * 16;
                uint32_t ah0[4], ah1[4], al0[4], al1[4], bf[4];
                ldm_x4(ah0, aHi0 + ka * 2);
                ldm_x4(ah1, aHi1 + ka * 2);
                ldm_x4(bf,  bs + ks * 32);          // {bh, bl} fused
                ldm_x4(al0, aLo0 + ka * 2);
                ldm_x4(al1, aLo1 + ka * 2);
                mma16816(acc + 0, ah0, bf);
                mma16816(acc + 4, ah1, bf);
                mma16816(acc + 0, ah0, bf + 2);
                mma16816(acc + 4, ah1, bf + 2);
                mma16816(acc + 0, al0, bf);
                mma16816(acc + 4, al1, bf);
            }
        }

        // ---- all-warp partial dump, all-thread epilogue ----
        {
            float* dst = red + (kq * 8) * 128 + wn * 32 + lane;
#pragma unroll
            for (int q = 0; q < 8; ++q) dst[q * 128] = acc[q];
        }
        __syncthreads();
        {
            float at = ax, gt = gx;
#pragma unroll
            for (int k2 = 0; k2 < 4; ++k2) {
                at += red[(k2 * 8 + p2) * 128 + aidx_base];
                gt += red[(k2 * 8 + 4 + p2) * 128 + aidx_base];
            }
            float z  = ux * tanhf(gt);
            float an = fmaxf(sa, at);
            float ed = expf(sa - an);
            float es = expf(at - an);
            sn = sn * ed + z * es;
            sd = sd * ed + es;
            float h = tanhf(sn / sd);
            sa = an;
            __nv_bfloat16 hi, lo;
            split_bf16(h, hi, lo);
            g_hshi[(size_t)(t + 1) * BC + bglob * C + cglob] = hi;
            g_hslo[(size_t)(t + 1) * BC + bglob * C + cglob] = lo;
        }
        __syncthreads();                       // h stores done CTA-wide
        if (tid == 0) {                        // barrier + 1-thread fence
            __threadfence();
            atomicAdd(&g_flag[bh][rot], 1u);
        }
    }

    out_n[bglob * C + cglob]    = sn;
    out_d[bglob * C + cglob]    = sd;
    out_h[bglob * C + cglob]    = tanhf(sn / sd);
    out_amax[bglob * C + cglob] = sa;
}

// ---------------- launch ---------------------------------------------------
extern "C" void kernel_launch(void* const* d_in, const int* in_sizes, int n_in,
                              void* d_out, int out_size) {
    (void)in_sizes; (void)n_in; (void)out_size;
    const float* x      = (const float*)d_in[0];
    const float* s      = (const float*)d_in[1];
    const float* n0     = (const float*)d_in[2];
    const float* d0     = (const float*)d_in[3];
    const float* h0     = (const float*)d_in[4];
    const float* amax0  = (const float*)d_in[5];
    const float* u_w    = (const float*)d_in[6];
    const float* u_b    = (const float*)d_in[7];
    const float* g_w    = (const float*)d_in[8];
    const float* g_b    = (const float*)d_in[9];
    const float* a_w    = (const float*)d_in[10];
    const float* o_w    = (const float*)d_in[11];
    const float* o_b    = (const float*)d_in[12];

    float* out        = (float*)d_out;
    float* out_outs   = out;
    float* out_s      = out + (size_t)B * T * KOUT;
    float* out_n      = out_s + C;
    float* out_d      = out_n + (size_t)B * C;
    float* out_h      = out_d + (size_t)B * C;
    float* out_amax   = out_h + (size_t)B * C;

    cudaFuncSetAttribute(rec_kernel, cudaFuncAttributeMaxDynamicSharedMemorySize, RSMEM);
    cudaFuncSetAttribute(pre_gemm_bf16, cudaFuncAttributeMaxDynamicSharedMemorySize, GSMEM);
    cudaFuncSetAttribute(out_gemm_bf16, cudaFuncAttributeMaxDynamicSharedMemorySize, GSMEM);

    wprep_rec<<<NCG * 32 * C / 256, 256>>>(g_w, a_w);
    xprep<<<(B * T * F) / 256, 256>>>(x);
    pwprep<<<(3 * C * F) / 256, 256>>>(u_w, g_w, a_w);
    owprep<<<(KOUT * C) / 256, 256>>>(o_w);
    hinit<<<(BC + 255) / 256, 256>>>(h0, s, out_s);
    pre_gemm_bf16<<<dim3(512, 48), 256, GSMEM>>>(u_b, g_b);
    rec_kernel<<<RCTA, RTHR, RSMEM>>>(n0, d0, amax0,
                                      out_n, out_d, out_h, out_amax);
    out_gemm_bf16<<<dim3(512, 4), 256, GSMEM>>>(o_b, out_outs);
}